// round 2
// baseline (speedup 1.0000x reference)
#include <cuda_runtime.h>
#include <math.h>

#define HEADS  8
#define LEVELS 4
#define POINTS 4
#define DIM    32
#define EMBED  256
#define NQ     1200
#define BS     8
#define NV     19560   // 92*160 + 46*80 + 23*40 + 12*20

#define OFF_N  256     // HEADS*LEVELS*POINTS*2
#define QO_N   384     // OFF_N + HEADS*LEVELS*POINTS (=128)

#define BM 128
#define BN 64
#define BK 16

// Scratch (allocation-free rule: device globals)
__device__ float g_v[(size_t)BS * HEADS * NV * DIM];   // (b, h, pix, d) : 160 MB
__device__ float g_qo[(size_t)BS * NQ * QO_N];         // offsets(256) || attn logits(128)
__device__ float g_att[(size_t)BS * NQ * EMBED];       // deformable-attn output

__constant__ int c_H[4]     = {92, 46, 23, 12};
__constant__ int c_W[4]     = {160, 80, 40, 20};
__constant__ int c_start[4] = {0, 14720, 18400, 19320};

// ---------------------------------------------------------------------------
// Generic fp32 GEMM, C[M,N] = A[M,256] @ B[256,N] (+epilogue), 128x64x16 tile,
// 256 threads, 8x4 micro-tile per thread.
// MODE 0: A=value,            B=Wv (N=256),      C=g_v scattered to (b,h,pix,d), +bv
// MODE 1: A=query+query_pos,  B=Wo||Wa (N=384),  C=g_qo, +bo||ba
// MODE 2: A=g_att,            B=Wout (N=256),    C=d_out, +bout +query (identity)
// ---------------------------------------------------------------------------
template <int MODE>
__global__ __launch_bounds__(256)
void gemm_k(const float* __restrict__ Aext, const float* __restrict__ A2,
            const float* __restrict__ B1,  const float* __restrict__ B2,
            const float* __restrict__ bias1, const float* __restrict__ bias2,
            const float* __restrict__ addsrc, float* __restrict__ Cext, int M)
{
    constexpr int N = (MODE == 1) ? QO_N : 256;
    constexpr int K = 256;

    const float* A = (MODE == 2) ? g_att : Aext;
    float* C = (MODE == 0) ? g_v : (MODE == 1) ? g_qo : Cext;

    __shared__ float As[BK][BM + 4];
    __shared__ float Bs[BK][BN];

    const int tid = threadIdx.x;
    const int block_m = blockIdx.y * BM;
    const int block_n = blockIdx.x * BN;

    const int a_row = tid >> 2;          // 0..63
    const int a_col = (tid & 3) * 4;     // 0,4,8,12
    const int b_row = tid >> 4;          // 0..15
    const int b_col = (tid & 15) * 4;    // 0..60

    const int tm = (tid >> 4) * 8;       // 0..120
    const int tn = (tid & 15) * 4;       // 0..60

    float acc[8][4];
#pragma unroll
    for (int i = 0; i < 8; i++)
#pragma unroll
        for (int j = 0; j < 4; j++) acc[i][j] = 0.f;

    for (int k0 = 0; k0 < K; k0 += BK) {
        // ---- load A tile (transposed into shared) ----
#pragma unroll
        for (int rr = 0; rr < 2; rr++) {
            int r = a_row + rr * 64;
            int gr = block_m + r;
            float4 v = make_float4(0.f, 0.f, 0.f, 0.f);
            if (gr < M) {
                v = *reinterpret_cast<const float4*>(A + (size_t)gr * K + k0 + a_col);
                if (MODE == 1) {
                    float4 v2 = *reinterpret_cast<const float4*>(A2 + (size_t)gr * K + k0 + a_col);
                    v.x += v2.x; v.y += v2.y; v.z += v2.z; v.w += v2.w;
                }
            }
            As[a_col + 0][r] = v.x;
            As[a_col + 1][r] = v.y;
            As[a_col + 2][r] = v.z;
            As[a_col + 3][r] = v.w;
        }
        // ---- load B tile ----
        {
            int gk = k0 + b_row;
            int gc = block_n + b_col;
            float4 v;
            if (MODE == 1) {
                if (gc < OFF_N) v = *reinterpret_cast<const float4*>(B1 + (size_t)gk * OFF_N + gc);
                else            v = *reinterpret_cast<const float4*>(B2 + (size_t)gk * 128 + (gc - OFF_N));
            } else {
                v = *reinterpret_cast<const float4*>(B1 + (size_t)gk * N + gc);
            }
            *reinterpret_cast<float4*>(&Bs[b_row][b_col]) = v;
        }
        __syncthreads();

#pragma unroll
        for (int k = 0; k < BK; k++) {
            float a[8], b[4];
#pragma unroll
            for (int i = 0; i < 8; i++) a[i] = As[k][tm + i];
#pragma unroll
            for (int j = 0; j < 4; j++) b[j] = Bs[k][tn + j];
#pragma unroll
            for (int i = 0; i < 8; i++)
#pragma unroll
                for (int j = 0; j < 4; j++)
                    acc[i][j] = fmaf(a[i], b[j], acc[i][j]);
        }
        __syncthreads();
    }

    // ---- epilogue ----
#pragma unroll
    for (int i = 0; i < 8; i++) {
        int gr = block_m + tm + i;
        if (gr >= M) continue;
        int gc0 = block_n + tn;
        if (MODE == 0) {
            int b  = gr / NV;
            int n  = gr - b * NV;
            int h  = gc0 >> 5;
            int d  = gc0 & 31;
            float4 o;
            o.x = acc[i][0] + bias1[gc0 + 0];
            o.y = acc[i][1] + bias1[gc0 + 1];
            o.z = acc[i][2] + bias1[gc0 + 2];
            o.w = acc[i][3] + bias1[gc0 + 3];
            size_t oidx = ((size_t)(b * HEADS + h) * NV + n) * DIM + d;
            *reinterpret_cast<float4*>(C + oidx) = o;
        } else if (MODE == 1) {
            float4 o;
            float bb[4];
#pragma unroll
            for (int j = 0; j < 4; j++) {
                int gc = gc0 + j;
                bb[j] = (gc < OFF_N) ? bias1[gc] : bias2[gc - OFF_N];
            }
            o.x = acc[i][0] + bb[0];
            o.y = acc[i][1] + bb[1];
            o.z = acc[i][2] + bb[2];
            o.w = acc[i][3] + bb[3];
            *reinterpret_cast<float4*>(C + (size_t)gr * QO_N + gc0) = o;
        } else {
            const float4 idv = *reinterpret_cast<const float4*>(addsrc + (size_t)gr * 256 + gc0);
            float4 o;
            o.x = acc[i][0] + bias1[gc0 + 0] + idv.x;
            o.y = acc[i][1] + bias1[gc0 + 1] + idv.y;
            o.z = acc[i][2] + bias1[gc0 + 2] + idv.z;
            o.w = acc[i][3] + bias1[gc0 + 3] + idv.w;
            *reinterpret_cast<float4*>(C + (size_t)gr * 256 + gc0) = o;
        }
    }
}

// ---------------------------------------------------------------------------
// Deformable sampling: one warp per (b, q, h); lane = channel (DIM=32).
// Fuses softmax over the 16 attention logits (warp shuffles) + bilinear gather.
// ---------------------------------------------------------------------------
__global__ __launch_bounds__(256)
void sample_kernel(const float* __restrict__ ref, const float* __restrict__ lro)
{
    int gw   = (blockIdx.x * blockDim.x + threadIdx.x) >> 5;
    int lane = threadIdx.x & 31;
    if (gw >= BS * NQ * HEADS) return;
    int h  = gw & 7;
    int bq = gw >> 3;                 // b*NQ + q
    int b  = bq / NQ;

    const float* row = g_qo + (size_t)bq * QO_N;

    // softmax over 16 logits
    float logit = (lane < 16) ? row[OFF_N + h * 16 + lane] : -1e30f;
    float m = logit;
#pragma unroll
    for (int s = 16; s; s >>= 1) m = fmaxf(m, __shfl_xor_sync(0xffffffffu, m, s));
    float e = (lane < 16) ? expf(logit - m) : 0.f;
    float ssum = e;
#pragma unroll
    for (int s = 16; s; s >>= 1) ssum += __shfl_xor_sync(0xffffffffu, ssum, s);
    float inv = 1.f / ssum;

    const float* vb = g_v + (size_t)(b * HEADS + h) * NV * DIM + lane;
    float lx = lro[(size_t)(bq * HEADS + h) * 2 + 0];
    float ly = lro[(size_t)(bq * HEADS + h) * 2 + 1];

    float acc = 0.f;
#pragma unroll
    for (int l = 0; l < 4; l++) {
        const int H  = c_H[l];
        const int W  = c_W[l];
        const int st = c_start[l];
        float rx = ref[(size_t)(bq * 4 + l) * 2 + 0];
        float ry = ref[(size_t)(bq * 4 + l) * 2 + 1];
#pragma unroll
        for (int p = 0; p < 4; p++) {
            int j = l * 4 + p;
            float ox = row[((h * 4 + l) * 4 + p) * 2 + 0];
            float oy = row[((h * 4 + l) * 4 + p) * 2 + 1];
            float px = (rx + ox / (float)W + lx) * (float)W - 0.5f;
            float py = (ry + oy / (float)H + ly) * (float)H - 0.5f;
            float a  = __shfl_sync(0xffffffffu, e, j) * inv;

            float x0f = floorf(px), y0f = floorf(py);
            int   x0  = (int)x0f,   y0  = (int)y0f;
            float wx1 = px - x0f,   wy1 = py - y0f;
            float wx0 = 1.f - wx1,  wy0 = 1.f - wy1;

            bool xi0 = (x0 >= 0) && (x0 < W);
            bool xi1 = (x0 + 1 >= 0) && (x0 + 1 < W);
            bool yi0 = (y0 >= 0) && (y0 < H);
            bool yi1 = (y0 + 1 >= 0) && (y0 + 1 < H);

            const float* base = vb + (size_t)st * DIM;
            float v00 = 0.f, v10 = 0.f, v01 = 0.f, v11 = 0.f;
            if (yi0) {
                long r0 = (long)y0 * W;
                if (xi0) v00 = base[(size_t)(r0 + x0) * DIM];
                if (xi1) v10 = base[(size_t)(r0 + x0 + 1) * DIM];
            }
            if (yi1) {
                long r1 = (long)(y0 + 1) * W;
                if (xi0) v01 = base[(size_t)(r1 + x0) * DIM];
                if (xi1) v11 = base[(size_t)(r1 + x0 + 1) * DIM];
            }
            acc += a * (wx0 * wy0 * v00 + wx1 * wy0 * v10 +
                        wx0 * wy1 * v01 + wx1 * wy1 * v11);
        }
    }
    g_att[(size_t)bq * EMBED + h * DIM + lane] = acc;
}

// ---------------------------------------------------------------------------
extern "C" void kernel_launch(void* const* d_in, const int* in_sizes, int n_in,
                              void* d_out, int out_size)
{
    (void)in_sizes; (void)n_in; (void)out_size;
    const float* query = (const float*)d_in[0];
    const float* value = (const float*)d_in[1];
    const float* qpos  = (const float*)d_in[2];
    const float* ref   = (const float*)d_in[3];
    const float* lro   = (const float*)d_in[4];
    // d_in[5] = spatial_shapes (int64) — compile-time constants here
    const float* Wv    = (const float*)d_in[6];
    const float* bv    = (const float*)d_in[7];
    const float* Wo    = (const float*)d_in[8];
    const float* bo    = (const float*)d_in[9];
    const float* Wa    = (const float*)d_in[10];
    const float* ba    = (const float*)d_in[11];
    const float* Wout  = (const float*)d_in[12];
    const float* bout  = (const float*)d_in[13];
    float* out = (float*)d_out;

    // 1) value projection -> g_v  (M=156480, N=256)
    {
        dim3 g(256 / BN, (BS * NV + BM - 1) / BM);
        gemm_k<0><<<g, 256>>>(value, nullptr, Wv, nullptr, bv, nullptr, nullptr, nullptr, BS * NV);
    }
    // 2) (query+query_pos) @ [Wo || Wa] -> g_qo  (M=9600, N=384)
    {
        dim3 g(QO_N / BN, (BS * NQ + BM - 1) / BM);
        gemm_k<1><<<g, 256>>>(query, qpos, Wo, Wa, bo, ba, nullptr, nullptr, BS * NQ);
    }
    // 3) softmax + bilinear sampling -> g_att
    {
        int total_threads = BS * NQ * HEADS * 32;
        sample_kernel<<<(total_threads + 255) / 256, 256>>>(ref, lro);
    }
    // 4) g_att @ Wout + bout + query -> out  (M=9600, N=256)
    {
        dim3 g(256 / BN, (BS * NQ + BM - 1) / BM);
        gemm_k<2><<<g, 256>>>(nullptr, nullptr, Wout, nullptr, bout, nullptr, query, out, BS * NQ);
    }
}

// round 3
// speedup vs baseline: 1.7229x; 1.7229x over previous
#include <cuda_runtime.h>
#include <math.h>
#include <stdint.h>

#define HEADS  8
#define LEVELS 4
#define POINTS 4
#define DIM    32
#define EMBED  256
#define NQ     1200
#define BS     8
#define NV     19560   // 92*160 + 46*80 + 23*40 + 12*20

#define OFF_N  256     // HEADS*LEVELS*POINTS*2
#define QO_N   384     // OFF_N + HEADS*LEVELS*POINTS (=128)

#define BM 128
#define BN 64
#define BK 16

// Scratch (allocation-free rule: device globals)
__device__ float g_v[(size_t)BS * HEADS * NV * DIM];   // (b, h, pix, d) : 160 MB
__device__ float g_qo[(size_t)BS * NQ * QO_N];         // offsets(256) || attn logits(128)
__device__ float g_att[(size_t)BS * NQ * EMBED];       // deformable-attn output

__constant__ int c_H[4]     = {92, 46, 23, 12};
__constant__ int c_W[4]     = {160, 80, 40, 20};
__constant__ int c_start[4] = {0, 14720, 18400, 19320};

// ===========================================================================
// Tensor-core (tf32 mma.sync) value-projection GEMM:
//   g_v[(b,h,pix,d)] = value[M,256] @ Wv[256,256] + bv
// 128x128x32 tile, 256 threads (8 warps as 2x4), warp tile 64x32,
// mma.m16n8k8.tf32. Conflict-free manual LDS fragment loads.
// ===========================================================================
__device__ __forceinline__ uint32_t f2tf32(float f) {
    uint32_t u;
    asm("cvt.rna.tf32.f32 %0, %1;" : "=r"(u) : "f"(f));
    return u;
}

__device__ __forceinline__ void mma_tf32(float& d0, float& d1, float& d2, float& d3,
                                         uint32_t a0, uint32_t a1, uint32_t a2, uint32_t a3,
                                         uint32_t b0, uint32_t b1) {
    asm volatile("mma.sync.aligned.m16n8k8.row.col.f32.tf32.tf32.f32 "
                 "{%0,%1,%2,%3},{%4,%5,%6,%7},{%8,%9},{%0,%1,%2,%3};"
                 : "+f"(d0), "+f"(d1), "+f"(d2), "+f"(d3)
                 : "r"(a0), "r"(a1), "r"(a2), "r"(a3), "r"(b0), "r"(b1));
}

#define AS_STRIDE 36    // 32 + 4 pad: bank = 4*tg + tig  (all 32 distinct)
#define BS_STRIDE 136   // 128 + 8 pad: bank = 8*tig + tg (all 32 distinct)

__global__ __launch_bounds__(256)
void gemm_v_tc(const float* __restrict__ A, const float* __restrict__ B,
               const float* __restrict__ bias, int M)
{
    __shared__ uint32_t As[128][AS_STRIDE];   // [m][k]
    __shared__ uint32_t Bsm[32][BS_STRIDE];   // [k][n]

    const int tid  = threadIdx.x;
    const int lane = tid & 31;
    const int warp = tid >> 5;
    const int wm   = warp >> 2;       // 0..1
    const int wn   = warp & 3;        // 0..3
    const int tg   = lane >> 2;       // 0..7 (groupID)
    const int tig  = lane & 3;        // 0..3

    const int block_m = blockIdx.y * 128;
    const int block_n = blockIdx.x * 128;

    float acc[4][4][4];
#pragma unroll
    for (int i = 0; i < 4; i++)
#pragma unroll
        for (int j = 0; j < 4; j++)
#pragma unroll
            for (int r = 0; r < 4; r++) acc[i][j][r] = 0.f;

    for (int k0 = 0; k0 < 256; k0 += 32) {
        // ---- A tile: 128 rows x 32 k (fp32 -> tf32) ----
#pragma unroll
        for (int i = 0; i < 4; i++) {
            int idx = tid + i * 256;         // 0..1023 float4 slots
            int row = idx >> 3;              // 0..127
            int c4  = idx & 7;               // 0..7
            int gr  = block_m + row;
            float4 v = make_float4(0.f, 0.f, 0.f, 0.f);
            if (gr < M)
                v = *reinterpret_cast<const float4*>(A + (size_t)gr * 256 + k0 + c4 * 4);
            uint4 u;
            u.x = f2tf32(v.x); u.y = f2tf32(v.y); u.z = f2tf32(v.z); u.w = f2tf32(v.w);
            *reinterpret_cast<uint4*>(&As[row][c4 * 4]) = u;
        }
        // ---- B tile: 32 k x 128 n ----
#pragma unroll
        for (int i = 0; i < 4; i++) {
            int idx  = tid + i * 256;
            int krow = idx >> 5;             // 0..31
            int n4   = idx & 31;             // 0..31
            float4 v = *reinterpret_cast<const float4*>(
                B + (size_t)(k0 + krow) * 256 + block_n + n4 * 4);
            uint4 u;
            u.x = f2tf32(v.x); u.y = f2tf32(v.y); u.z = f2tf32(v.z); u.w = f2tf32(v.w);
            *reinterpret_cast<uint4*>(&Bsm[krow][n4 * 4]) = u;
        }
        __syncthreads();

#pragma unroll
        for (int ks = 0; ks < 4; ks++) {
            const int k = ks * 8;
            uint32_t a[4][4], b[4][2];
#pragma unroll
            for (int mt = 0; mt < 4; mt++) {
                int m = wm * 64 + mt * 16 + tg;
                a[mt][0] = As[m][k + tig];
                a[mt][1] = As[m + 8][k + tig];
                a[mt][2] = As[m][k + tig + 4];
                a[mt][3] = As[m + 8][k + tig + 4];
            }
#pragma unroll
            for (int nt = 0; nt < 4; nt++) {
                int n = wn * 32 + nt * 8 + tg;
                b[nt][0] = Bsm[k + tig][n];
                b[nt][1] = Bsm[k + tig + 4][n];
            }
#pragma unroll
            for (int mt = 0; mt < 4; mt++)
#pragma unroll
                for (int nt = 0; nt < 4; nt++)
                    mma_tf32(acc[mt][nt][0], acc[mt][nt][1], acc[mt][nt][2], acc[mt][nt][3],
                             a[mt][0], a[mt][1], a[mt][2], a[mt][3],
                             b[nt][0], b[nt][1]);
        }
        __syncthreads();
    }

    // ---- epilogue: scatter to g_v (b, h, pix, d) + bias ----
#pragma unroll
    for (int mt = 0; mt < 4; mt++) {
#pragma unroll
        for (int nt = 0; nt < 4; nt++) {
            int gc = block_n + wn * 32 + nt * 8 + 2 * tig;   // 0..255, even
            int h  = gc >> 5;
            int d  = gc & 31;
            float bx = bias[gc], by = bias[gc + 1];
#pragma unroll
            for (int rr = 0; rr < 2; rr++) {
                int gr = block_m + wm * 64 + mt * 16 + tg + rr * 8;
                if (gr >= M) continue;
                int b  = gr / NV;
                int n  = gr - b * NV;
                float2 o;
                o.x = acc[mt][nt][rr * 2 + 0] + bx;
                o.y = acc[mt][nt][rr * 2 + 1] + by;
                size_t oidx = ((size_t)(b * HEADS + h) * NV + n) * DIM + d;
                *reinterpret_cast<float2*>(g_v + oidx) = o;
            }
        }
    }
}

// ---------------------------------------------------------------------------
// fp32 SIMT GEMM for the small GEMMs, 128x64x16 tile.
// MODE 1: A=query+query_pos,  B=Wo||Wa (N=384),  C=g_qo, +bo||ba
// MODE 2: A=g_att,            B=Wout (N=256),    C=d_out, +bout +query
// ---------------------------------------------------------------------------
template <int MODE>
__global__ __launch_bounds__(256)
void gemm_k(const float* __restrict__ Aext, const float* __restrict__ A2,
            const float* __restrict__ B1,  const float* __restrict__ B2,
            const float* __restrict__ bias1, const float* __restrict__ bias2,
            const float* __restrict__ addsrc, float* __restrict__ Cext, int M)
{
    constexpr int N = (MODE == 1) ? QO_N : 256;
    constexpr int K = 256;

    const float* A = (MODE == 2) ? g_att : Aext;
    float* C = (MODE == 1) ? g_qo : Cext;

    __shared__ float As[BK][BM + 4];
    __shared__ float Bs[BK][BN];

    const int tid = threadIdx.x;
    const int block_m = blockIdx.y * BM;
    const int block_n = blockIdx.x * BN;

    const int a_row = tid >> 2;
    const int a_col = (tid & 3) * 4;
    const int b_row = tid >> 4;
    const int b_col = (tid & 15) * 4;

    const int tm = (tid >> 4) * 8;
    const int tn = (tid & 15) * 4;

    float acc[8][4];
#pragma unroll
    for (int i = 0; i < 8; i++)
#pragma unroll
        for (int j = 0; j < 4; j++) acc[i][j] = 0.f;

    for (int k0 = 0; k0 < K; k0 += BK) {
#pragma unroll
        for (int rr = 0; rr < 2; rr++) {
            int r = a_row + rr * 64;
            int gr = block_m + r;
            float4 v = make_float4(0.f, 0.f, 0.f, 0.f);
            if (gr < M) {
                v = *reinterpret_cast<const float4*>(A + (size_t)gr * K + k0 + a_col);
                if (MODE == 1) {
                    float4 v2 = *reinterpret_cast<const float4*>(A2 + (size_t)gr * K + k0 + a_col);
                    v.x += v2.x; v.y += v2.y; v.z += v2.z; v.w += v2.w;
                }
            }
            As[a_col + 0][r] = v.x;
            As[a_col + 1][r] = v.y;
            As[a_col + 2][r] = v.z;
            As[a_col + 3][r] = v.w;
        }
        {
            int gk = k0 + b_row;
            int gc = block_n + b_col;
            float4 v;
            if (MODE == 1) {
                if (gc < OFF_N) v = *reinterpret_cast<const float4*>(B1 + (size_t)gk * OFF_N + gc);
                else            v = *reinterpret_cast<const float4*>(B2 + (size_t)gk * 128 + (gc - OFF_N));
            } else {
                v = *reinterpret_cast<const float4*>(B1 + (size_t)gk * N + gc);
            }
            *reinterpret_cast<float4*>(&Bs[b_row][b_col]) = v;
        }
        __syncthreads();

#pragma unroll
        for (int k = 0; k < BK; k++) {
            float a[8], b[4];
#pragma unroll
            for (int i = 0; i < 8; i++) a[i] = As[k][tm + i];
#pragma unroll
            for (int j = 0; j < 4; j++) b[j] = Bs[k][tn + j];
#pragma unroll
            for (int i = 0; i < 8; i++)
#pragma unroll
                for (int j = 0; j < 4; j++)
                    acc[i][j] = fmaf(a[i], b[j], acc[i][j]);
        }
        __syncthreads();
    }

#pragma unroll
    for (int i = 0; i < 8; i++) {
        int gr = block_m + tm + i;
        if (gr >= M) continue;
        int gc0 = block_n + tn;
        if (MODE == 1) {
            float4 o;
            float bb[4];
#pragma unroll
            for (int j = 0; j < 4; j++) {
                int gc = gc0 + j;
                bb[j] = (gc < OFF_N) ? bias1[gc] : bias2[gc - OFF_N];
            }
            o.x = acc[i][0] + bb[0];
            o.y = acc[i][1] + bb[1];
            o.z = acc[i][2] + bb[2];
            o.w = acc[i][3] + bb[3];
            *reinterpret_cast<float4*>(C + (size_t)gr * QO_N + gc0) = o;
        } else {
            const float4 idv = *reinterpret_cast<const float4*>(addsrc + (size_t)gr * 256 + gc0);
            float4 o;
            o.x = acc[i][0] + bias1[gc0 + 0] + idv.x;
            o.y = acc[i][1] + bias1[gc0 + 1] + idv.y;
            o.z = acc[i][2] + bias1[gc0 + 2] + idv.z;
            o.w = acc[i][3] + bias1[gc0 + 3] + idv.w;
            *reinterpret_cast<float4*>(C + (size_t)gr * 256 + gc0) = o;
        }
    }
}

// ---------------------------------------------------------------------------
// Deformable sampling: one warp per (b, q, h); lane = channel (DIM=32).
// ---------------------------------------------------------------------------
__global__ __launch_bounds__(256)
void sample_kernel(const float* __restrict__ ref, const float* __restrict__ lro)
{
    int gw   = (blockIdx.x * blockDim.x + threadIdx.x) >> 5;
    int lane = threadIdx.x & 31;
    if (gw >= BS * NQ * HEADS) return;
    int h  = gw & 7;
    int bq = gw >> 3;
    int b  = bq / NQ;

    const float* row = g_qo + (size_t)bq * QO_N;

    float logit = (lane < 16) ? row[OFF_N + h * 16 + lane] : -1e30f;
    float m = logit;
#pragma unroll
    for (int s = 16; s; s >>= 1) m = fmaxf(m, __shfl_xor_sync(0xffffffffu, m, s));
    float e = (lane < 16) ? expf(logit - m) : 0.f;
    float ssum = e;
#pragma unroll
    for (int s = 16; s; s >>= 1) ssum += __shfl_xor_sync(0xffffffffu, ssum, s);
    float inv = 1.f / ssum;

    const float* vb = g_v + (size_t)(b * HEADS + h) * NV * DIM + lane;
    float lx = lro[(size_t)(bq * HEADS + h) * 2 + 0];
    float ly = lro[(size_t)(bq * HEADS + h) * 2 + 1];

    float acc = 0.f;
#pragma unroll
    for (int l = 0; l < 4; l++) {
        const int H  = c_H[l];
        const int W  = c_W[l];
        const int st = c_start[l];
        float rx = ref[(size_t)(bq * 4 + l) * 2 + 0];
        float ry = ref[(size_t)(bq * 4 + l) * 2 + 1];
#pragma unroll
        for (int p = 0; p < 4; p++) {
            int j = l * 4 + p;
            float ox = row[((h * 4 + l) * 4 + p) * 2 + 0];
            float oy = row[((h * 4 + l) * 4 + p) * 2 + 1];
            float px = (rx + ox / (float)W + lx) * (float)W - 0.5f;
            float py = (ry + oy / (float)H + ly) * (float)H - 0.5f;
            float a  = __shfl_sync(0xffffffffu, e, j) * inv;

            float x0f = floorf(px), y0f = floorf(py);
            int   x0  = (int)x0f,   y0  = (int)y0f;
            float wx1 = px - x0f,   wy1 = py - y0f;
            float wx0 = 1.f - wx1,  wy0 = 1.f - wy1;

            bool xi0 = (x0 >= 0) && (x0 < W);
            bool xi1 = (x0 + 1 >= 0) && (x0 + 1 < W);
            bool yi0 = (y0 >= 0) && (y0 < H);
            bool yi1 = (y0 + 1 >= 0) && (y0 + 1 < H);

            const float* base = vb + (size_t)st * DIM;
            float v00 = 0.f, v10 = 0.f, v01 = 0.f, v11 = 0.f;
            if (yi0) {
                long r0 = (long)y0 * W;
                if (xi0) v00 = base[(size_t)(r0 + x0) * DIM];
                if (xi1) v10 = base[(size_t)(r0 + x0 + 1) * DIM];
            }
            if (yi1) {
                long r1 = (long)(y0 + 1) * W;
                if (xi0) v01 = base[(size_t)(r1 + x0) * DIM];
                if (xi1) v11 = base[(size_t)(r1 + x0 + 1) * DIM];
            }
            acc += a * (wx0 * wy0 * v00 + wx1 * wy0 * v10 +
                        wx0 * wy1 * v01 + wx1 * wy1 * v11);
        }
    }
    g_att[(size_t)bq * EMBED + h * DIM + lane] = acc;
}

// ---------------------------------------------------------------------------
extern "C" void kernel_launch(void* const* d_in, const int* in_sizes, int n_in,
                              void* d_out, int out_size)
{
    (void)in_sizes; (void)n_in; (void)out_size;
    const float* query = (const float*)d_in[0];
    const float* value = (const float*)d_in[1];
    const float* qpos  = (const float*)d_in[2];
    const float* ref   = (const float*)d_in[3];
    const float* lro   = (const float*)d_in[4];
    const float* Wv    = (const float*)d_in[6];
    const float* bv    = (const float*)d_in[7];
    const float* Wo    = (const float*)d_in[8];
    const float* bo    = (const float*)d_in[9];
    const float* Wa    = (const float*)d_in[10];
    const float* ba    = (const float*)d_in[11];
    const float* Wout  = (const float*)d_in[12];
    const float* bout  = (const float*)d_in[13];
    float* out = (float*)d_out;

    // 1) value projection -> g_v  (M=156480, N=256) : tensor cores (tf32)
    {
        dim3 g(2, (BS * NV + 127) / 128);
        gemm_v_tc<<<g, 256>>>(value, Wv, bv, BS * NV);
    }
    // 2) (query+query_pos) @ [Wo || Wa] -> g_qo  (M=9600, N=384)
    {
        dim3 g(QO_N / BN, (BS * NQ + BM - 1) / BM);
        gemm_k<1><<<g, 256>>>(query, qpos, Wo, Wa, bo, ba, nullptr, nullptr, BS * NQ);
    }
    // 3) softmax + bilinear sampling -> g_att
    {
        int total_threads = BS * NQ * HEADS * 32;
        sample_kernel<<<(total_threads + 255) / 256, 256>>>(ref, lro);
    }
    // 4) g_att @ Wout + bout + query -> out  (M=9600, N=256)
    {
        dim3 g(256 / BN, (BS * NQ + BM - 1) / BM);
        gemm_k<2><<<g, 256>>>(nullptr, nullptr, Wout, nullptr, bout, nullptr, query, out, BS * NQ);
    }
}

// round 4
// speedup vs baseline: 2.0075x; 1.1652x over previous
#include <cuda_runtime.h>
#include <cuda_fp16.h>
#include <math.h>
#include <stdint.h>

#define HEADS  8
#define LEVELS 4
#define POINTS 4
#define DIM    32
#define EMBED  256
#define NQ     1200
#define BS     8
#define NV     19560   // 92*160 + 46*80 + 23*40 + 12*20

#define OFF_N  256     // HEADS*LEVELS*POINTS*2
#define QO_N   384     // OFF_N + 128 logits

// Scratch (allocation-free rule: device globals)
__device__ __half g_v_h[(size_t)BS * HEADS * NV * DIM];  // (b,h,pix,d) fp16 : 80 MB
__device__ float  g_qo[(size_t)BS * NQ * QO_N];          // offsets(256) || logits(128)
__device__ float  g_att[(size_t)BS * NQ * EMBED];        // deformable-attn output

__constant__ int c_H[4]     = {92, 46, 23, 12};
__constant__ int c_W[4]     = {160, 80, 40, 20};
__constant__ int c_start[4] = {0, 14720, 18400, 19320};

// ===========================================================================
// tf32 mma.sync GEMM, 128x128x32 tile, 256 threads (2x4 warps), warp 64x32,
// register-prefetch pipeline (LDG next tile issued before mma on current).
// MODE 0: A=value,           B=Wv,      +bv,        C -> g_v_h fp16 scatter (b,h,pix,d)
// MODE 1: A=query+qpos,      B=Wo||Wa,  +bo||ba,    C -> g_qo fp32 (N=384)
// MODE 2: A=g_att,           B=Wout,    +bout+query,C -> d_out fp32
// ===========================================================================
__device__ __forceinline__ uint32_t f2tf32(float f) {
    uint32_t u;
    asm("cvt.rna.tf32.f32 %0, %1;" : "=r"(u) : "f"(f));
    return u;
}

__device__ __forceinline__ void mma_tf32(float& d0, float& d1, float& d2, float& d3,
                                         uint32_t a0, uint32_t a1, uint32_t a2, uint32_t a3,
                                         uint32_t b0, uint32_t b1) {
    asm volatile("mma.sync.aligned.m16n8k8.row.col.f32.tf32.tf32.f32 "
                 "{%0,%1,%2,%3},{%4,%5,%6,%7},{%8,%9},{%0,%1,%2,%3};"
                 : "+f"(d0), "+f"(d1), "+f"(d2), "+f"(d3)
                 : "r"(a0), "r"(a1), "r"(a2), "r"(a3), "r"(b0), "r"(b1));
}

#define AS_STRIDE 36    // 32+4 pad: frag-load banks 4*tg+tig all distinct
#define BS_STRIDE 136   // 128+8 pad: frag-load banks 8*tig+tg all distinct

template <int MODE>
__global__ __launch_bounds__(256)
void gemm_tc(const float* __restrict__ Aext, const float* __restrict__ A2,
             const float* __restrict__ B1,  const float* __restrict__ B2,
             const float* __restrict__ bias1, const float* __restrict__ bias2,
             const float* __restrict__ addsrc, float* __restrict__ Cext, int M)
{
    __shared__ uint32_t As[128][AS_STRIDE];   // [m][k]
    __shared__ uint32_t Bsm[32][BS_STRIDE];   // [k][n]

    const float* A = (MODE == 2) ? g_att : Aext;

    const int tid  = threadIdx.x;
    const int lane = tid & 31;
    const int warp = tid >> 5;
    const int wm   = warp >> 2;       // 0..1
    const int wn   = warp & 3;        // 0..3
    const int tg   = lane >> 2;       // 0..7
    const int tig  = lane & 3;        // 0..3

    const int block_m = blockIdx.y * 128;
    const int block_n = blockIdx.x * 128;

    float acc[4][4][4];
#pragma unroll
    for (int i = 0; i < 4; i++)
#pragma unroll
        for (int j = 0; j < 4; j++)
#pragma unroll
            for (int r = 0; r < 4; r++) acc[i][j][r] = 0.f;

    // staging registers for one 128x32 A tile + 32x128 B tile
    float4 aS[4], bS[4];

    // per-thread copy geometry
    const int a_row0 = tid >> 3;        // with +32*i
    const int a_c4   = (tid & 7) * 4;   // k offset (floats)
    const int b_k0   = tid >> 5;        // with +8*i
    const int b_n4   = (lane) * 4;      // n offset (floats)

    auto ldgA = [&](int k0) {
#pragma unroll
        for (int i = 0; i < 4; i++) {
            int row = a_row0 + i * 32;
            int gr  = block_m + row;
            float4 v = make_float4(0.f, 0.f, 0.f, 0.f);
            if (gr < M) {
                v = *reinterpret_cast<const float4*>(A + (size_t)gr * 256 + k0 + a_c4);
                if (MODE == 1) {
                    float4 v2 = *reinterpret_cast<const float4*>(A2 + (size_t)gr * 256 + k0 + a_c4);
                    v.x += v2.x; v.y += v2.y; v.z += v2.z; v.w += v2.w;
                }
            }
            aS[i] = v;
        }
    };
    auto ldgB = [&](int k0) {
#pragma unroll
        for (int i = 0; i < 4; i++) {
            int krow = b_k0 + i * 8;
            int gc   = block_n + b_n4;
            float4 v;
            if (MODE == 1) {
                if (gc < OFF_N) v = *reinterpret_cast<const float4*>(B1 + (size_t)(k0 + krow) * OFF_N + gc);
                else            v = *reinterpret_cast<const float4*>(B2 + (size_t)(k0 + krow) * 128 + (gc - OFF_N));
            } else {
                v = *reinterpret_cast<const float4*>(B1 + (size_t)(k0 + krow) * 256 + gc);
            }
            bS[i] = v;
        }
    };
    auto sts = [&]() {
#pragma unroll
        for (int i = 0; i < 4; i++) {
            uint4 u;
            u.x = f2tf32(aS[i].x); u.y = f2tf32(aS[i].y);
            u.z = f2tf32(aS[i].z); u.w = f2tf32(aS[i].w);
            *reinterpret_cast<uint4*>(&As[a_row0 + i * 32][a_c4]) = u;
        }
#pragma unroll
        for (int i = 0; i < 4; i++) {
            uint4 u;
            u.x = f2tf32(bS[i].x); u.y = f2tf32(bS[i].y);
            u.z = f2tf32(bS[i].z); u.w = f2tf32(bS[i].w);
            *reinterpret_cast<uint4*>(&Bsm[b_k0 + i * 8][b_n4]) = u;
        }
    };

    ldgA(0); ldgB(0);

    for (int k0 = 0; k0 < 256; k0 += 32) {
        sts();
        __syncthreads();
        if (k0 + 32 < 256) { ldgA(k0 + 32); ldgB(k0 + 32); }  // overlap with mma

#pragma unroll
        for (int ks = 0; ks < 4; ks++) {
            const int k = ks * 8;
            uint32_t a[4][4], b[4][2];
#pragma unroll
            for (int mt = 0; mt < 4; mt++) {
                int m = wm * 64 + mt * 16 + tg;
                a[mt][0] = As[m][k + tig];
                a[mt][1] = As[m + 8][k + tig];
                a[mt][2] = As[m][k + tig + 4];
                a[mt][3] = As[m + 8][k + tig + 4];
            }
#pragma unroll
            for (int nt = 0; nt < 4; nt++) {
                int n = wn * 32 + nt * 8 + tg;
                b[nt][0] = Bsm[k + tig][n];
                b[nt][1] = Bsm[k + tig + 4][n];
            }
#pragma unroll
            for (int mt = 0; mt < 4; mt++)
#pragma unroll
                for (int nt = 0; nt < 4; nt++)
                    mma_tf32(acc[mt][nt][0], acc[mt][nt][1], acc[mt][nt][2], acc[mt][nt][3],
                             a[mt][0], a[mt][1], a[mt][2], a[mt][3],
                             b[nt][0], b[nt][1]);
        }
        __syncthreads();
    }

    // ---- epilogue ----
#pragma unroll
    for (int mt = 0; mt < 4; mt++) {
#pragma unroll
        for (int nt = 0; nt < 4; nt++) {
            int gc = block_n + wn * 32 + nt * 8 + 2 * tig;   // even col
            float bx, by;
            if (MODE == 1) {
                bx = (gc < OFF_N) ? bias1[gc] : bias2[gc - OFF_N];
                by = (gc + 1 < OFF_N) ? bias1[gc + 1] : bias2[gc + 1 - OFF_N];
            } else {
                bx = bias1[gc]; by = bias1[gc + 1];
            }
#pragma unroll
            for (int rr = 0; rr < 2; rr++) {
                int gr = block_m + wm * 64 + mt * 16 + tg + rr * 8;
                if (gr >= M) continue;
                float ox = acc[mt][nt][rr * 2 + 0] + bx;
                float oy = acc[mt][nt][rr * 2 + 1] + by;
                if (MODE == 0) {
                    int b  = gr / NV;
                    int n  = gr - b * NV;
                    int h  = gc >> 5;
                    int d  = gc & 31;
                    size_t oidx = ((size_t)(b * HEADS + h) * NV + n) * DIM + d;
                    *reinterpret_cast<__half2*>(g_v_h + oidx) = __floats2half2_rn(ox, oy);
                } else if (MODE == 1) {
                    float2 o; o.x = ox; o.y = oy;
                    *reinterpret_cast<float2*>(g_qo + (size_t)gr * QO_N + gc) = o;
                } else {
                    const float2 idv = *reinterpret_cast<const float2*>(addsrc + (size_t)gr * 256 + gc);
                    float2 o; o.x = ox + idv.x; o.y = oy + idv.y;
                    *reinterpret_cast<float2*>(Cext + (size_t)gr * 256 + gc) = o;
                }
            }
        }
    }
}

// ---------------------------------------------------------------------------
// Deformable sampling: one warp per (b, q, h); lane = channel (DIM=32).
// g_v_h is fp16 -> 64B per corner row (half the traffic of fp32).
// ---------------------------------------------------------------------------
__global__ __launch_bounds__(256)
void sample_kernel(const float* __restrict__ ref, const float* __restrict__ lro)
{
    int gw   = (blockIdx.x * blockDim.x + threadIdx.x) >> 5;
    int lane = threadIdx.x & 31;
    if (gw >= BS * NQ * HEADS) return;
    int h  = gw & 7;
    int bq = gw >> 3;
    int b  = bq / NQ;

    const float* row = g_qo + (size_t)bq * QO_N;

    float logit = (lane < 16) ? row[OFF_N + h * 16 + lane] : -1e30f;
    float m = logit;
#pragma unroll
    for (int s = 16; s; s >>= 1) m = fmaxf(m, __shfl_xor_sync(0xffffffffu, m, s));
    float e = (lane < 16) ? expf(logit - m) : 0.f;
    float ssum = e;
#pragma unroll
    for (int s = 16; s; s >>= 1) ssum += __shfl_xor_sync(0xffffffffu, ssum, s);
    float inv = 1.f / ssum;

    const __half* vb = g_v_h + (size_t)(b * HEADS + h) * NV * DIM + lane;
    float lx = lro[(size_t)(bq * HEADS + h) * 2 + 0];
    float ly = lro[(size_t)(bq * HEADS + h) * 2 + 1];

    float acc = 0.f;
#pragma unroll
    for (int l = 0; l < 4; l++) {
        const int H  = c_H[l];
        const int W  = c_W[l];
        const int st = c_start[l];
        float rx = ref[(size_t)(bq * 4 + l) * 2 + 0];
        float ry = ref[(size_t)(bq * 4 + l) * 2 + 1];
#pragma unroll
        for (int p = 0; p < 4; p++) {
            int j = l * 4 + p;
            float ox = row[((h * 4 + l) * 4 + p) * 2 + 0];
            float oy = row[((h * 4 + l) * 4 + p) * 2 + 1];
            float px = (rx + ox / (float)W + lx) * (float)W - 0.5f;
            float py = (ry + oy / (float)H + ly) * (float)H - 0.5f;
            float a  = __shfl_sync(0xffffffffu, e, j) * inv;

            float x0f = floorf(px), y0f = floorf(py);
            int   x0  = (int)x0f,   y0  = (int)y0f;
            float wx1 = px - x0f,   wy1 = py - y0f;
            float wx0 = 1.f - wx1,  wy0 = 1.f - wy1;

            bool xi0 = (x0 >= 0) && (x0 < W);
            bool xi1 = (x0 + 1 >= 0) && (x0 + 1 < W);
            bool yi0 = (y0 >= 0) && (y0 < H);
            bool yi1 = (y0 + 1 >= 0) && (y0 + 1 < H);

            const __half* base = vb + (size_t)st * DIM;
            float v00 = 0.f, v10 = 0.f, v01 = 0.f, v11 = 0.f;
            if (yi0) {
                long r0 = (long)y0 * W;
                if (xi0) v00 = __half2float(base[(size_t)(r0 + x0) * DIM]);
                if (xi1) v10 = __half2float(base[(size_t)(r0 + x0 + 1) * DIM]);
            }
            if (yi1) {
                long r1 = (long)(y0 + 1) * W;
                if (xi0) v01 = __half2float(base[(size_t)(r1 + x0) * DIM]);
                if (xi1) v11 = __half2float(base[(size_t)(r1 + x0 + 1) * DIM]);
            }
            acc += a * (wx0 * wy0 * v00 + wx1 * wy0 * v10 +
                        wx0 * wy1 * v01 + wx1 * wy1 * v11);
        }
    }
    g_att[(size_t)bq * EMBED + h * DIM + lane] = acc;
}

// ---------------------------------------------------------------------------
extern "C" void kernel_launch(void* const* d_in, const int* in_sizes, int n_in,
                              void* d_out, int out_size)
{
    (void)in_sizes; (void)n_in; (void)out_size;
    const float* query = (const float*)d_in[0];
    const float* value = (const float*)d_in[1];
    const float* qpos  = (const float*)d_in[2];
    const float* ref   = (const float*)d_in[3];
    const float* lro   = (const float*)d_in[4];
    const float* Wv    = (const float*)d_in[6];
    const float* bv    = (const float*)d_in[7];
    const float* Wo    = (const float*)d_in[8];
    const float* bo    = (const float*)d_in[9];
    const float* Wa    = (const float*)d_in[10];
    const float* ba    = (const float*)d_in[11];
    const float* Wout  = (const float*)d_in[12];
    const float* bout  = (const float*)d_in[13];
    float* out = (float*)d_out;

    // 1) value projection -> g_v_h fp16  (M=156480, N=256)
    {
        dim3 g(2, (BS * NV + 127) / 128);
        gemm_tc<0><<<g, 256>>>(value, nullptr, Wv, nullptr, bv, nullptr, nullptr, nullptr, BS * NV);
    }
    // 2) (query+query_pos) @ [Wo || Wa] -> g_qo  (M=9600, N=384)
    {
        dim3 g(3, (BS * NQ + 127) / 128);
        gemm_tc<1><<<g, 256>>>(query, qpos, Wo, Wa, bo, ba, nullptr, nullptr, BS * NQ);
    }
    // 3) softmax + bilinear sampling -> g_att
    {
        int total_threads = BS * NQ * HEADS * 32;
        sample_kernel<<<(total_threads + 255) / 256, 256>>>(ref, lro);
    }
    // 4) g_att @ Wout + bout + query -> out  (M=9600, N=256)
    {
        dim3 g(2, (BS * NQ + 127) / 128);
        gemm_tc<2><<<g, 256>>>(nullptr, nullptr, Wout, nullptr, bout, nullptr, query, out, BS * NQ);
    }
}

// round 5
// speedup vs baseline: 2.2560x; 1.1238x over previous
#include <cuda_runtime.h>
#include <cuda_fp16.h>
#include <cuda_bf16.h>
#include <math.h>
#include <stdint.h>

#define HEADS  8
#define LEVELS 4
#define POINTS 4
#define DIM    32
#define EMBED  256
#define NQ     1200
#define BS     8
#define NV     19560   // 92*160 + 46*80 + 23*40 + 12*20

#define OFF_N  256     // HEADS*LEVELS*POINTS*2
#define QO_N   384     // OFF_N + 128 logits

// Scratch (allocation-free rule: device globals)
__device__ __half    g_v_h[(size_t)BS * HEADS * NV * DIM]; // (b,h,pix,d) fp16 : 80 MB
__device__ float     g_qo[(size_t)BS * NQ * QO_N];         // offsets(256) || logits(128)
__device__ float     g_att[(size_t)BS * NQ * EMBED];       // deformable-attn output
__device__ uint32_t  g_wvT[256 * 128];                     // Wv as bf16 pairs, [n][kk]

__constant__ int c_H[4]     = {92, 46, 23, 12};
__constant__ int c_W[4]     = {160, 80, 40, 20};
__constant__ int c_start[4] = {0, 14720, 18400, 19320};

// ---------------------------------------------------------------------------
// Pre-convert Wv[256x256] fp32 (k-major rows) -> g_wvT bf16 pairs [n][kk]
// pair kk holds (k=2kk, k=2kk+1) for column n.
// ---------------------------------------------------------------------------
__global__ __launch_bounds__(256)
void conv_wv(const float* __restrict__ Wv)
{
    int idx = blockIdx.x * 256 + threadIdx.x;   // 0..32767
    int n  = idx >> 7;
    int kk = idx & 127;
    float lo = Wv[(size_t)(2 * kk) * 256 + n];
    float hi = Wv[(size_t)(2 * kk + 1) * 256 + n];
    __nv_bfloat162 p = __floats2bfloat162_rn(lo, hi);
    g_wvT[n * 128 + kk] = *reinterpret_cast<uint32_t*>(&p);
}

// ===========================================================================
// bf16 mma.m16n8k16 value-projection GEMM:
//   g_v_h[(b,h,pix,d)] = half(value[M,256] @ Wv + bv)
// 128x128x32 tile, 256 threads (2x4 warps), warp 64x32, register prefetch.
// ===========================================================================
__device__ __forceinline__ void mma_bf16(float& d0, float& d1, float& d2, float& d3,
                                         uint32_t a0, uint32_t a1, uint32_t a2, uint32_t a3,
                                         uint32_t b0, uint32_t b1) {
    asm volatile("mma.sync.aligned.m16n8k16.row.col.f32.bf16.bf16.f32 "
                 "{%0,%1,%2,%3},{%4,%5,%6,%7},{%8,%9},{%0,%1,%2,%3};"
                 : "+f"(d0), "+f"(d1), "+f"(d2), "+f"(d3)
                 : "r"(a0), "r"(a1), "r"(a2), "r"(a3), "r"(b0), "r"(b1));
}

#define PSTRIDE 20   // 16 pairs + 4 pad (uint32): tg*20+tig distinct mod 32

__global__ __launch_bounds__(256)
void gemm_v_bf16(const float* __restrict__ A, const float* __restrict__ bias, int M)
{
    __shared__ uint32_t As[128][PSTRIDE];   // [m][kpair]
    __shared__ uint32_t Bsm[128][PSTRIDE];  // [n][kpair]

    const int tid  = threadIdx.x;
    const int lane = tid & 31;
    const int warp = tid >> 5;
    const int wm   = warp >> 2;
    const int wn   = warp & 3;
    const int tg   = lane >> 2;
    const int tig  = lane & 3;

    const int block_m = blockIdx.y * 128;
    const int block_n = blockIdx.x * 128;

    float acc[4][4][4];
#pragma unroll
    for (int i = 0; i < 4; i++)
#pragma unroll
        for (int j = 0; j < 4; j++)
#pragma unroll
            for (int r = 0; r < 4; r++) acc[i][j][r] = 0.f;

    // staging regs
    float4 aS[4];
    uint4  bU[2];

    const int a_row0 = tid >> 3;        // + 32*i
    const int a_c4   = (tid & 7) * 4;   // float k offset
    const int b_n    = tid >> 1;        // 0..127
    const int b_s0   = (tid & 1) * 2;   // uint4 slot base (0 or 2)

    auto ldgA = [&](int k0) {
#pragma unroll
        for (int i = 0; i < 4; i++) {
            int gr = block_m + a_row0 + i * 32;
            float4 v = make_float4(0.f, 0.f, 0.f, 0.f);
            if (gr < M)
                v = *reinterpret_cast<const float4*>(A + (size_t)gr * 256 + k0 + a_c4);
            aS[i] = v;
        }
    };
    auto ldgB = [&](int k0) {
        int kk0 = k0 >> 1;
#pragma unroll
        for (int j = 0; j < 2; j++)
            bU[j] = *reinterpret_cast<const uint4*>(
                &g_wvT[(block_n + b_n) * 128 + kk0 + (b_s0 + j) * 4]);
    };
    auto sts = [&]() {
#pragma unroll
        for (int i = 0; i < 4; i++) {
            __nv_bfloat162 p0 = __floats2bfloat162_rn(aS[i].x, aS[i].y);
            __nv_bfloat162 p1 = __floats2bfloat162_rn(aS[i].z, aS[i].w);
            uint2 u;
            u.x = *reinterpret_cast<uint32_t*>(&p0);
            u.y = *reinterpret_cast<uint32_t*>(&p1);
            *reinterpret_cast<uint2*>(&As[a_row0 + i * 32][(a_c4 >> 1)]) = u;
        }
#pragma unroll
        for (int j = 0; j < 2; j++)
            *reinterpret_cast<uint4*>(&Bsm[b_n][(b_s0 + j) * 4]) = bU[j];
    };

    ldgA(0); ldgB(0);

    for (int k0 = 0; k0 < 256; k0 += 32) {
        sts();
        __syncthreads();
        if (k0 + 32 < 256) { ldgA(k0 + 32); ldgB(k0 + 32); }

#pragma unroll
        for (int s = 0; s < 2; s++) {          // two k16 steps
            const int p0 = s * 8;
            uint32_t a[4][4], b[4][2];
#pragma unroll
            for (int mt = 0; mt < 4; mt++) {
                int m = wm * 64 + mt * 16 + tg;
                a[mt][0] = As[m][p0 + tig];
                a[mt][1] = As[m + 8][p0 + tig];
                a[mt][2] = As[m][p0 + tig + 4];
                a[mt][3] = As[m + 8][p0 + tig + 4];
            }
#pragma unroll
            for (int nt = 0; nt < 4; nt++) {
                int n = wn * 32 + nt * 8 + tg;
                b[nt][0] = Bsm[n][p0 + tig];
                b[nt][1] = Bsm[n][p0 + tig + 4];
            }
#pragma unroll
            for (int mt = 0; mt < 4; mt++)
#pragma unroll
                for (int nt = 0; nt < 4; nt++)
                    mma_bf16(acc[mt][nt][0], acc[mt][nt][1], acc[mt][nt][2], acc[mt][nt][3],
                             a[mt][0], a[mt][1], a[mt][2], a[mt][3],
                             b[nt][0], b[nt][1]);
        }
        __syncthreads();
    }

    // epilogue: scatter fp16 to g_v_h (b, h, pix, d) + bias
#pragma unroll
    for (int mt = 0; mt < 4; mt++) {
#pragma unroll
        for (int nt = 0; nt < 4; nt++) {
            int gc = block_n + wn * 32 + nt * 8 + 2 * tig;
            int h  = gc >> 5;
            int d  = gc & 31;
            float bx = bias[gc], by = bias[gc + 1];
#pragma unroll
            for (int rr = 0; rr < 2; rr++) {
                int gr = block_m + wm * 64 + mt * 16 + tg + rr * 8;
                if (gr >= M) continue;
                int b = gr / NV;
                int n = gr - b * NV;
                size_t oidx = ((size_t)(b * HEADS + h) * NV + n) * DIM + d;
                *reinterpret_cast<__half2*>(g_v_h + oidx) =
                    __floats2half2_rn(acc[mt][nt][rr * 2 + 0] + bx,
                                      acc[mt][nt][rr * 2 + 1] + by);
            }
        }
    }
}

// ===========================================================================
// tf32 mma.sync GEMM for the small GEMMs (modes 1,2), as in R3/R4.
// ===========================================================================
__device__ __forceinline__ uint32_t f2tf32(float f) {
    uint32_t u;
    asm("cvt.rna.tf32.f32 %0, %1;" : "=r"(u) : "f"(f));
    return u;
}

__device__ __forceinline__ void mma_tf32(float& d0, float& d1, float& d2, float& d3,
                                         uint32_t a0, uint32_t a1, uint32_t a2, uint32_t a3,
                                         uint32_t b0, uint32_t b1) {
    asm volatile("mma.sync.aligned.m16n8k8.row.col.f32.tf32.tf32.f32 "
                 "{%0,%1,%2,%3},{%4,%5,%6,%7},{%8,%9},{%0,%1,%2,%3};"
                 : "+f"(d0), "+f"(d1), "+f"(d2), "+f"(d3)
                 : "r"(a0), "r"(a1), "r"(a2), "r"(a3), "r"(b0), "r"(b1));
}

#define AS_STRIDE 36
#define BS_STRIDE 136

template <int MODE>
__global__ __launch_bounds__(256)
void gemm_tc(const float* __restrict__ Aext, const float* __restrict__ A2,
             const float* __restrict__ B1,  const float* __restrict__ B2,
             const float* __restrict__ bias1, const float* __restrict__ bias2,
             const float* __restrict__ addsrc, float* __restrict__ Cext, int M)
{
    __shared__ uint32_t As[128][AS_STRIDE];
    __shared__ uint32_t Bsm[32][BS_STRIDE];

    const float* A = (MODE == 2) ? g_att : Aext;

    const int tid  = threadIdx.x;
    const int lane = tid & 31;
    const int warp = tid >> 5;
    const int wm   = warp >> 2;
    const int wn   = warp & 3;
    const int tg   = lane >> 2;
    const int tig  = lane & 3;

    const int block_m = blockIdx.y * 128;
    const int block_n = blockIdx.x * 128;

    float acc[4][4][4];
#pragma unroll
    for (int i = 0; i < 4; i++)
#pragma unroll
        for (int j = 0; j < 4; j++)
#pragma unroll
            for (int r = 0; r < 4; r++) acc[i][j][r] = 0.f;

    float4 aS[4], bS[4];
    const int a_row0 = tid >> 3;
    const int a_c4   = (tid & 7) * 4;
    const int b_k0   = tid >> 5;
    const int b_n4   = lane * 4;

    auto ldgA = [&](int k0) {
#pragma unroll
        for (int i = 0; i < 4; i++) {
            int gr = block_m + a_row0 + i * 32;
            float4 v = make_float4(0.f, 0.f, 0.f, 0.f);
            if (gr < M) {
                v = *reinterpret_cast<const float4*>(A + (size_t)gr * 256 + k0 + a_c4);
                if (MODE == 1) {
                    float4 v2 = *reinterpret_cast<const float4*>(A2 + (size_t)gr * 256 + k0 + a_c4);
                    v.x += v2.x; v.y += v2.y; v.z += v2.z; v.w += v2.w;
                }
            }
            aS[i] = v;
        }
    };
    auto ldgB = [&](int k0) {
#pragma unroll
        for (int i = 0; i < 4; i++) {
            int krow = b_k0 + i * 8;
            int gc   = block_n + b_n4;
            float4 v;
            if (MODE == 1) {
                if (gc < OFF_N) v = *reinterpret_cast<const float4*>(B1 + (size_t)(k0 + krow) * OFF_N + gc);
                else            v = *reinterpret_cast<const float4*>(B2 + (size_t)(k0 + krow) * 128 + (gc - OFF_N));
            } else {
                v = *reinterpret_cast<const float4*>(B1 + (size_t)(k0 + krow) * 256 + gc);
            }
            bS[i] = v;
        }
    };
    auto sts = [&]() {
#pragma unroll
        for (int i = 0; i < 4; i++) {
            uint4 u;
            u.x = f2tf32(aS[i].x); u.y = f2tf32(aS[i].y);
            u.z = f2tf32(aS[i].z); u.w = f2tf32(aS[i].w);
            *reinterpret_cast<uint4*>(&As[a_row0 + i * 32][a_c4]) = u;
        }
#pragma unroll
        for (int i = 0; i < 4; i++) {
            uint4 u;
            u.x = f2tf32(bS[i].x); u.y = f2tf32(bS[i].y);
            u.z = f2tf32(bS[i].z); u.w = f2tf32(bS[i].w);
            *reinterpret_cast<uint4*>(&Bsm[b_k0 + i * 8][b_n4]) = u;
        }
    };

    ldgA(0); ldgB(0);

    for (int k0 = 0; k0 < 256; k0 += 32) {
        sts();
        __syncthreads();
        if (k0 + 32 < 256) { ldgA(k0 + 32); ldgB(k0 + 32); }

#pragma unroll
        for (int ks = 0; ks < 4; ks++) {
            const int k = ks * 8;
            uint32_t a[4][4], b[4][2];
#pragma unroll
            for (int mt = 0; mt < 4; mt++) {
                int m = wm * 64 + mt * 16 + tg;
                a[mt][0] = As[m][k + tig];
                a[mt][1] = As[m + 8][k + tig];
                a[mt][2] = As[m][k + tig + 4];
                a[mt][3] = As[m + 8][k + tig + 4];
            }
#pragma unroll
            for (int nt = 0; nt < 4; nt++) {
                int n = wn * 32 + nt * 8 + tg;
                b[nt][0] = Bsm[k + tig][n];
                b[nt][1] = Bsm[k + tig + 4][n];
            }
#pragma unroll
            for (int mt = 0; mt < 4; mt++)
#pragma unroll
                for (int nt = 0; nt < 4; nt++)
                    mma_tf32(acc[mt][nt][0], acc[mt][nt][1], acc[mt][nt][2], acc[mt][nt][3],
                             a[mt][0], a[mt][1], a[mt][2], a[mt][3],
                             b[nt][0], b[nt][1]);
        }
        __syncthreads();
    }

#pragma unroll
    for (int mt = 0; mt < 4; mt++) {
#pragma unroll
        for (int nt = 0; nt < 4; nt++) {
            int gc = block_n + wn * 32 + nt * 8 + 2 * tig;
            float bx, by;
            if (MODE == 1) {
                bx = (gc < OFF_N) ? bias1[gc] : bias2[gc - OFF_N];
                by = (gc + 1 < OFF_N) ? bias1[gc + 1] : bias2[gc + 1 - OFF_N];
            } else {
                bx = bias1[gc]; by = bias1[gc + 1];
            }
#pragma unroll
            for (int rr = 0; rr < 2; rr++) {
                int gr = block_m + wm * 64 + mt * 16 + tg + rr * 8;
                if (gr >= M) continue;
                float ox = acc[mt][nt][rr * 2 + 0] + bx;
                float oy = acc[mt][nt][rr * 2 + 1] + by;
                if (MODE == 1) {
                    float2 o; o.x = ox; o.y = oy;
                    *reinterpret_cast<float2*>(g_qo + (size_t)gr * QO_N + gc) = o;
                } else {
                    const float2 idv = *reinterpret_cast<const float2*>(addsrc + (size_t)gr * 256 + gc);
                    float2 o; o.x = ox + idv.x; o.y = oy + idv.y;
                    *reinterpret_cast<float2*>(Cext + (size_t)gr * 256 + gc) = o;
                }
            }
        }
    }
}

// ---------------------------------------------------------------------------
// Deformable sampling: one warp per (b, q, h); lane = channel (DIM=32).
// ---------------------------------------------------------------------------
__global__ __launch_bounds__(256)
void sample_kernel(const float* __restrict__ ref, const float* __restrict__ lro)
{
    int gw   = (blockIdx.x * blockDim.x + threadIdx.x) >> 5;
    int lane = threadIdx.x & 31;
    if (gw >= BS * NQ * HEADS) return;
    int h  = gw & 7;
    int bq = gw >> 3;
    int b  = bq / NQ;

    const float* row = g_qo + (size_t)bq * QO_N;

    float logit = (lane < 16) ? row[OFF_N + h * 16 + lane] : -1e30f;
    float m = logit;
#pragma unroll
    for (int s = 16; s; s >>= 1) m = fmaxf(m, __shfl_xor_sync(0xffffffffu, m, s));
    float e = (lane < 16) ? expf(logit - m) : 0.f;
    float ssum = e;
#pragma unroll
    for (int s = 16; s; s >>= 1) ssum += __shfl_xor_sync(0xffffffffu, ssum, s);
    float inv = 1.f / ssum;

    const __half* vb = g_v_h + (size_t)(b * HEADS + h) * NV * DIM + lane;
    float lx = lro[(size_t)(bq * HEADS + h) * 2 + 0];
    float ly = lro[(size_t)(bq * HEADS + h) * 2 + 1];

    float acc = 0.f;
#pragma unroll
    for (int l = 0; l < 4; l++) {
        const int H  = c_H[l];
        const int W  = c_W[l];
        const int st = c_start[l];
        float rx = ref[(size_t)(bq * 4 + l) * 2 + 0];
        float ry = ref[(size_t)(bq * 4 + l) * 2 + 1];
#pragma unroll
        for (int p = 0; p < 4; p++) {
            int j = l * 4 + p;
            float ox = row[((h * 4 + l) * 4 + p) * 2 + 0];
            float oy = row[((h * 4 + l) * 4 + p) * 2 + 1];
            float px = (rx + ox / (float)W + lx) * (float)W - 0.5f;
            float py = (ry + oy / (float)H + ly) * (float)H - 0.5f;
            float a  = __shfl_sync(0xffffffffu, e, j) * inv;

            float x0f = floorf(px), y0f = floorf(py);
            int   x0  = (int)x0f,   y0  = (int)y0f;
            float wx1 = px - x0f,   wy1 = py - y0f;
            float wx0 = 1.f - wx1,  wy0 = 1.f - wy1;

            bool xi0 = (x0 >= 0) && (x0 < W);
            bool xi1 = (x0 + 1 >= 0) && (x0 + 1 < W);
            bool yi0 = (y0 >= 0) && (y0 < H);
            bool yi1 = (y0 + 1 >= 0) && (y0 + 1 < H);

            const __half* base = vb + (size_t)st * DIM;
            float v00 = 0.f, v10 = 0.f, v01 = 0.f, v11 = 0.f;
            if (yi0) {
                long r0 = (long)y0 * W;
                if (xi0) v00 = __half2float(base[(size_t)(r0 + x0) * DIM]);
                if (xi1) v10 = __half2float(base[(size_t)(r0 + x0 + 1) * DIM]);
            }
            if (yi1) {
                long r1 = (long)(y0 + 1) * W;
                if (xi0) v01 = __half2float(base[(size_t)(r1 + x0) * DIM]);
                if (xi1) v11 = __half2float(base[(size_t)(r1 + x0 + 1) * DIM]);
            }
            acc += a * (wx0 * wy0 * v00 + wx1 * wy0 * v10 +
                        wx0 * wy1 * v01 + wx1 * wy1 * v11);
        }
    }
    g_att[(size_t)bq * EMBED + h * DIM + lane] = acc;
}

// ---------------------------------------------------------------------------
extern "C" void kernel_launch(void* const* d_in, const int* in_sizes, int n_in,
                              void* d_out, int out_size)
{
    (void)in_sizes; (void)n_in; (void)out_size;
    const float* query = (const float*)d_in[0];
    const float* value = (const float*)d_in[1];
    const float* qpos  = (const float*)d_in[2];
    const float* ref   = (const float*)d_in[3];
    const float* lro   = (const float*)d_in[4];
    const float* Wv    = (const float*)d_in[6];
    const float* bv    = (const float*)d_in[7];
    const float* Wo    = (const float*)d_in[8];
    const float* bo    = (const float*)d_in[9];
    const float* Wa    = (const float*)d_in[10];
    const float* ba    = (const float*)d_in[11];
    const float* Wout  = (const float*)d_in[12];
    const float* bout  = (const float*)d_in[13];
    float* out = (float*)d_out;

    // 0) convert Wv -> bf16 transposed pairs
    conv_wv<<<128, 256>>>(Wv);
    // 1) value projection -> g_v_h fp16 (bf16 tensor cores)
    {
        dim3 g(2, (BS * NV + 127) / 128);
        gemm_v_bf16<<<g, 256>>>(value, bv, BS * NV);
    }
    // 2) (query+query_pos) @ [Wo || Wa] -> g_qo
    {
        dim3 g(3, (BS * NQ + 127) / 128);
        gemm_tc<1><<<g, 256>>>(query, qpos, Wo, Wa, bo, ba, nullptr, nullptr, BS * NQ);
    }
    // 3) softmax + bilinear sampling -> g_att
    {
        int total_threads = BS * NQ * HEADS * 32;
        sample_kernel<<<(total_threads + 255) / 256, 256>>>(ref, lro);
    }
    // 4) g_att @ Wout + bout + query -> out
    {
        dim3 g(2, (BS * NQ + 127) / 128);
        gemm_tc<2><<<g, 256>>>(nullptr, nullptr, Wout, nullptr, bout, nullptr, query, out, BS * NQ);
    }
}

// round 6
// speedup vs baseline: 2.6597x; 1.1789x over previous
#include <cuda_runtime.h>
#include <cuda_fp16.h>
#include <cuda_bf16.h>
#include <math.h>
#include <stdint.h>

#define HEADS  8
#define LEVELS 4
#define POINTS 4
#define DIM    32
#define EMBED  256
#define NQ     1200
#define BS     8
#define NV     19560   // 92*160 + 46*80 + 23*40 + 12*20

#define OFF_N  256
#define QO_N   384

// Scratch (allocation-free rule: device globals)
__device__ __half    g_v_h[(size_t)BS * HEADS * NV * DIM]; // (b,h,pix,d) fp16 : 80 MB
__device__ float     g_qo[(size_t)BS * NQ * QO_N];         // offsets(256) || logits(128)
__device__ float     g_att[(size_t)BS * NQ * EMBED];
__device__ uint32_t  g_wvT[256 * 128];                     // Wv bf16 pairs [n][kk]

__constant__ int   c_H[4]    = {92, 46, 23, 12};
__constant__ int   c_W[4]    = {160, 80, 40, 20};
__constant__ int   c_start[4]= {0, 14720, 18400, 19320};
__constant__ float c_Hf[4]   = {92.f, 46.f, 23.f, 12.f};
__constant__ float c_Wf[4]   = {160.f, 80.f, 40.f, 20.f};
__constant__ float c_invH[4] = {1.f/92.f, 1.f/46.f, 1.f/23.f, 1.f/12.f};
__constant__ float c_invW[4] = {1.f/160.f, 1.f/80.f, 1.f/40.f, 1.f/20.f};

// ---------------------------------------------------------------------------
__global__ __launch_bounds__(256)
void conv_wv(const float* __restrict__ Wv)
{
    int idx = blockIdx.x * 256 + threadIdx.x;
    int n  = idx >> 7;
    int kk = idx & 127;
    float lo = Wv[(size_t)(2 * kk) * 256 + n];
    float hi = Wv[(size_t)(2 * kk + 1) * 256 + n];
    __nv_bfloat162 p = __floats2bfloat162_rn(lo, hi);
    g_wvT[n * 128 + kk] = *reinterpret_cast<uint32_t*>(&p);
}

// ===========================================================================
// bf16 mma.m16n8k16 value GEMM, 128x128x32, double-buffered smem.
// ===========================================================================
__device__ __forceinline__ void mma_bf16(float& d0, float& d1, float& d2, float& d3,
                                         uint32_t a0, uint32_t a1, uint32_t a2, uint32_t a3,
                                         uint32_t b0, uint32_t b1) {
    asm volatile("mma.sync.aligned.m16n8k16.row.col.f32.bf16.bf16.f32 "
                 "{%0,%1,%2,%3},{%4,%5,%6,%7},{%8,%9},{%0,%1,%2,%3};"
                 : "+f"(d0), "+f"(d1), "+f"(d2), "+f"(d3)
                 : "r"(a0), "r"(a1), "r"(a2), "r"(a3), "r"(b0), "r"(b1));
}

#define PSTRIDE 20

__global__ __launch_bounds__(256)
void gemm_v_bf16(const float* __restrict__ A, const float* __restrict__ bias, int M)
{
    __shared__ uint32_t As[2][128][PSTRIDE];
    __shared__ uint32_t Bsm[2][128][PSTRIDE];

    const int tid  = threadIdx.x;
    const int lane = tid & 31;
    const int warp = tid >> 5;
    const int wm   = warp >> 2;
    const int wn   = warp & 3;
    const int tg   = lane >> 2;
    const int tig  = lane & 3;

    const int block_m = blockIdx.y * 128;
    const int block_n = blockIdx.x * 128;

    float acc[4][4][4];
#pragma unroll
    for (int i = 0; i < 4; i++)
#pragma unroll
        for (int j = 0; j < 4; j++)
#pragma unroll
            for (int r = 0; r < 4; r++) acc[i][j][r] = 0.f;

    float4 aS[4];
    uint4  bU[2];

    const int a_row0 = tid >> 3;
    const int a_c4   = (tid & 7) * 4;
    const int b_n    = tid >> 1;
    const int b_s0   = (tid & 1) * 2;

    auto ldgA = [&](int k0) {
#pragma unroll
        for (int i = 0; i < 4; i++) {
            int gr = block_m + a_row0 + i * 32;
            float4 v = make_float4(0.f, 0.f, 0.f, 0.f);
            if (gr < M)
                v = *reinterpret_cast<const float4*>(A + (size_t)gr * 256 + k0 + a_c4);
            aS[i] = v;
        }
    };
    auto ldgB = [&](int k0) {
        int kk0 = k0 >> 1;
#pragma unroll
        for (int j = 0; j < 2; j++)
            bU[j] = *reinterpret_cast<const uint4*>(
                &g_wvT[(block_n + b_n) * 128 + kk0 + (b_s0 + j) * 4]);
    };
    auto sts = [&](int buf) {
#pragma unroll
        for (int i = 0; i < 4; i++) {
            __nv_bfloat162 p0 = __floats2bfloat162_rn(aS[i].x, aS[i].y);
            __nv_bfloat162 p1 = __floats2bfloat162_rn(aS[i].z, aS[i].w);
            uint2 u;
            u.x = *reinterpret_cast<uint32_t*>(&p0);
            u.y = *reinterpret_cast<uint32_t*>(&p1);
            *reinterpret_cast<uint2*>(&As[buf][a_row0 + i * 32][(a_c4 >> 1)]) = u;
        }
#pragma unroll
        for (int j = 0; j < 2; j++)
            *reinterpret_cast<uint4*>(&Bsm[buf][b_n][(b_s0 + j) * 4]) = bU[j];
    };

    ldgA(0); ldgB(0);
    sts(0);
    __syncthreads();

#pragma unroll
    for (int it = 0; it < 8; it++) {
        const int cur = it & 1;
        if (it < 7) { ldgA((it + 1) * 32); ldgB((it + 1) * 32); }

#pragma unroll
        for (int s = 0; s < 2; s++) {
            const int p0 = s * 8;
            uint32_t a[4][4], b[4][2];
#pragma unroll
            for (int mt = 0; mt < 4; mt++) {
                int m = wm * 64 + mt * 16 + tg;
                a[mt][0] = As[cur][m][p0 + tig];
                a[mt][1] = As[cur][m + 8][p0 + tig];
                a[mt][2] = As[cur][m][p0 + tig + 4];
                a[mt][3] = As[cur][m + 8][p0 + tig + 4];
            }
#pragma unroll
            for (int nt = 0; nt < 4; nt++) {
                int n = wn * 32 + nt * 8 + tg;
                b[nt][0] = Bsm[cur][n][p0 + tig];
                b[nt][1] = Bsm[cur][n][p0 + tig + 4];
            }
#pragma unroll
            for (int mt = 0; mt < 4; mt++)
#pragma unroll
                for (int nt = 0; nt < 4; nt++)
                    mma_bf16(acc[mt][nt][0], acc[mt][nt][1], acc[mt][nt][2], acc[mt][nt][3],
                             a[mt][0], a[mt][1], a[mt][2], a[mt][3],
                             b[nt][0], b[nt][1]);
        }
        if (it < 7) sts(cur ^ 1);
        __syncthreads();
    }

    // epilogue: scatter fp16 to g_v_h (b, h, pix, d) + bias
#pragma unroll
    for (int mt = 0; mt < 4; mt++) {
#pragma unroll
        for (int nt = 0; nt < 4; nt++) {
            int gc = block_n + wn * 32 + nt * 8 + 2 * tig;
            int h  = gc >> 5;
            int d  = gc & 31;
            float bx = bias[gc], by = bias[gc + 1];
#pragma unroll
            for (int rr = 0; rr < 2; rr++) {
                int gr = block_m + wm * 64 + mt * 16 + tg + rr * 8;
                if (gr >= M) continue;
                int b = gr / NV;
                int n = gr - b * NV;
                size_t oidx = ((size_t)(b * HEADS + h) * NV + n) * DIM + d;
                *reinterpret_cast<__half2*>(g_v_h + oidx) =
                    __floats2half2_rn(acc[mt][nt][rr * 2 + 0] + bx,
                                      acc[mt][nt][rr * 2 + 1] + by);
            }
        }
    }
}

// ===========================================================================
// tf32 mma.sync GEMM for modes 1,2 (unchanged from R4).
// ===========================================================================
__device__ __forceinline__ uint32_t f2tf32(float f) {
    uint32_t u;
    asm("cvt.rna.tf32.f32 %0, %1;" : "=r"(u) : "f"(f));
    return u;
}

__device__ __forceinline__ void mma_tf32(float& d0, float& d1, float& d2, float& d3,
                                         uint32_t a0, uint32_t a1, uint32_t a2, uint32_t a3,
                                         uint32_t b0, uint32_t b1) {
    asm volatile("mma.sync.aligned.m16n8k8.row.col.f32.tf32.tf32.f32 "
                 "{%0,%1,%2,%3},{%4,%5,%6,%7},{%8,%9},{%0,%1,%2,%3};"
                 : "+f"(d0), "+f"(d1), "+f"(d2), "+f"(d3)
                 : "r"(a0), "r"(a1), "r"(a2), "r"(a3), "r"(b0), "r"(b1));
}

#define AS_STRIDE 36
#define BS_STRIDE 136

template <int MODE>
__global__ __launch_bounds__(256)
void gemm_tc(const float* __restrict__ Aext, const float* __restrict__ A2,
             const float* __restrict__ B1,  const float* __restrict__ B2,
             const float* __restrict__ bias1, const float* __restrict__ bias2,
             const float* __restrict__ addsrc, float* __restrict__ Cext, int M)
{
    __shared__ uint32_t As[128][AS_STRIDE];
    __shared__ uint32_t Bsm[32][BS_STRIDE];

    const float* A = (MODE == 2) ? g_att : Aext;

    const int tid  = threadIdx.x;
    const int lane = tid & 31;
    const int warp = tid >> 5;
    const int wm   = warp >> 2;
    const int wn   = warp & 3;
    const int tg   = lane >> 2;
    const int tig  = lane & 3;

    const int block_m = blockIdx.y * 128;
    const int block_n = blockIdx.x * 128;

    float acc[4][4][4];
#pragma unroll
    for (int i = 0; i < 4; i++)
#pragma unroll
        for (int j = 0; j < 4; j++)
#pragma unroll
            for (int r = 0; r < 4; r++) acc[i][j][r] = 0.f;

    float4 aS[4], bS[4];
    const int a_row0 = tid >> 3;
    const int a_c4   = (tid & 7) * 4;
    const int b_k0   = tid >> 5;
    const int b_n4   = lane * 4;

    auto ldgA = [&](int k0) {
#pragma unroll
        for (int i = 0; i < 4; i++) {
            int gr = block_m + a_row0 + i * 32;
            float4 v = make_float4(0.f, 0.f, 0.f, 0.f);
            if (gr < M) {
                v = *reinterpret_cast<const float4*>(A + (size_t)gr * 256 + k0 + a_c4);
                if (MODE == 1) {
                    float4 v2 = *reinterpret_cast<const float4*>(A2 + (size_t)gr * 256 + k0 + a_c4);
                    v.x += v2.x; v.y += v2.y; v.z += v2.z; v.w += v2.w;
                }
            }
            aS[i] = v;
        }
    };
    auto ldgB = [&](int k0) {
#pragma unroll
        for (int i = 0; i < 4; i++) {
            int krow = b_k0 + i * 8;
            int gc   = block_n + b_n4;
            float4 v;
            if (MODE == 1) {
                if (gc < OFF_N) v = *reinterpret_cast<const float4*>(B1 + (size_t)(k0 + krow) * OFF_N + gc);
                else            v = *reinterpret_cast<const float4*>(B2 + (size_t)(k0 + krow) * 128 + (gc - OFF_N));
            } else {
                v = *reinterpret_cast<const float4*>(B1 + (size_t)(k0 + krow) * 256 + gc);
            }
            bS[i] = v;
        }
    };
    auto sts = [&]() {
#pragma unroll
        for (int i = 0; i < 4; i++) {
            uint4 u;
            u.x = f2tf32(aS[i].x); u.y = f2tf32(aS[i].y);
            u.z = f2tf32(aS[i].z); u.w = f2tf32(aS[i].w);
            *reinterpret_cast<uint4*>(&As[a_row0 + i * 32][a_c4]) = u;
        }
#pragma unroll
        for (int i = 0; i < 4; i++) {
            uint4 u;
            u.x = f2tf32(bS[i].x); u.y = f2tf32(bS[i].y);
            u.z = f2tf32(bS[i].z); u.w = f2tf32(bS[i].w);
            *reinterpret_cast<uint4*>(&Bsm[b_k0 + i * 8][b_n4]) = u;
        }
    };

    ldgA(0); ldgB(0);

    for (int k0 = 0; k0 < 256; k0 += 32) {
        sts();
        __syncthreads();
        if (k0 + 32 < 256) { ldgA(k0 + 32); ldgB(k0 + 32); }

#pragma unroll
        for (int ks = 0; ks < 4; ks++) {
            const int k = ks * 8;
            uint32_t a[4][4], b[4][2];
#pragma unroll
            for (int mt = 0; mt < 4; mt++) {
                int m = wm * 64 + mt * 16 + tg;
                a[mt][0] = As[m][k + tig];
                a[mt][1] = As[m + 8][k + tig];
                a[mt][2] = As[m][k + tig + 4];
                a[mt][3] = As[m + 8][k + tig + 4];
            }
#pragma unroll
            for (int nt = 0; nt < 4; nt++) {
                int n = wn * 32 + nt * 8 + tg;
                b[nt][0] = Bsm[k + tig][n];
                b[nt][1] = Bsm[k + tig + 4][n];
            }
#pragma unroll
            for (int mt = 0; mt < 4; mt++)
#pragma unroll
                for (int nt = 0; nt < 4; nt++)
                    mma_tf32(acc[mt][nt][0], acc[mt][nt][1], acc[mt][nt][2], acc[mt][nt][3],
                             a[mt][0], a[mt][1], a[mt][2], a[mt][3],
                             b[nt][0], b[nt][1]);
        }
        __syncthreads();
    }

#pragma unroll
    for (int mt = 0; mt < 4; mt++) {
#pragma unroll
        for (int nt = 0; nt < 4; nt++) {
            int gc = block_n + wn * 32 + nt * 8 + 2 * tig;
            float bx, by;
            if (MODE == 1) {
                bx = (gc < OFF_N) ? bias1[gc] : bias2[gc - OFF_N];
                by = (gc + 1 < OFF_N) ? bias1[gc + 1] : bias2[gc + 1 - OFF_N];
            } else {
                bx = bias1[gc]; by = bias1[gc + 1];
            }
#pragma unroll
            for (int rr = 0; rr < 2; rr++) {
                int gr = block_m + wm * 64 + mt * 16 + tg + rr * 8;
                if (gr >= M) continue;
                float ox = acc[mt][nt][rr * 2 + 0] + bx;
                float oy = acc[mt][nt][rr * 2 + 1] + by;
                if (MODE == 1) {
                    float2 o; o.x = ox; o.y = oy;
                    *reinterpret_cast<float2*>(g_qo + (size_t)gr * QO_N + gc) = o;
                } else {
                    const float2 idv = *reinterpret_cast<const float2*>(addsrc + (size_t)gr * 256 + gc);
                    float2 o; o.x = ox + idv.x; o.y = oy + idv.y;
                    *reinterpret_cast<float2*>(Cext + (size_t)gr * 256 + gc) = o;
                }
            }
        }
    }
}

// ===========================================================================
// Sampling v2: one warp = (b,q, head-pair). Half-warp hi owns head 2hp+hi;
// lane-within-half j owns point j. Phase A computes (softmax + coords +
// masked premultiplied weights + clamped indices) once, lane-parallel.
// Phase B: 16 x {7 shuffles + 4 coalesced half2 gathers + FMA}.
// ===========================================================================
__global__ __launch_bounds__(256)
void sample_kernel2(const float* __restrict__ ref, const float* __restrict__ lro)
{
    int gwarp = (blockIdx.x * blockDim.x + threadIdx.x) >> 5;
    int lane  = threadIdx.x & 31;
    int hp    = gwarp & 3;
    int bq    = gwarp >> 2;
    if (bq >= BS * NQ) return;
    int b  = bq / NQ;
    int hi = lane >> 4;
    int li = lane & 15;
    int h  = hp * 2 + hi;

    const float* row = g_qo + (size_t)bq * QO_N;

    // ---- softmax over 16 logits, per half-warp; lane li holds logit li ----
    float logit = row[OFF_N + h * 16 + li];
    float m = logit;
#pragma unroll
    for (int s = 8; s; s >>= 1) m = fmaxf(m, __shfl_xor_sync(0xffffffffu, m, s));
    float e = expf(logit - m);
    float ss = e;
#pragma unroll
    for (int s = 8; s; s >>= 1) ss += __shfl_xor_sync(0xffffffffu, ss, s);
    float a = e / ss;       // attention weight for point li of head h

    // ---- phase A: this lane = point j=li of head h ----
    int l = li >> 2;
    int p = li & 3;
    int W = c_W[l], H = c_H[l], st = c_start[l];

    float rx = ref[(size_t)(bq * 4 + l) * 2 + 0];
    float ry = ref[(size_t)(bq * 4 + l) * 2 + 1];
    float lx = lro[(size_t)(bq * 8 + h) * 2 + 0];
    float ly = lro[(size_t)(bq * 8 + h) * 2 + 1];
    float ox = row[((h * 4 + l) * 4 + p) * 2 + 0];
    float oy = row[((h * 4 + l) * 4 + p) * 2 + 1];

    float px = (rx + ox * c_invW[l] + lx) * c_Wf[l] - 0.5f;
    float py = (ry + oy * c_invH[l] + ly) * c_Hf[l] - 0.5f;

    float x0f = floorf(px), y0f = floorf(py);
    int   x0  = (int)x0f,   y0  = (int)y0f;
    float wx1 = px - x0f, wx0 = 1.f - wx1;
    float wy1 = py - y0f, wy0 = 1.f - wy1;

    float vx0 = (x0 >= 0 && x0 < W)         ? wx0 : 0.f;
    float vx1 = (x0 + 1 >= 0 && x0 + 1 < W) ? wx1 : 0.f;
    float vy0 = (y0 >= 0 && y0 < H)         ? wy0 : 0.f;
    float vy1 = (y0 + 1 >= 0 && y0 + 1 < H) ? wy1 : 0.f;

    float wA = a * vy0 * vx0;
    float wB = a * vy0 * vx1;
    float wC = a * vy1 * vx0;
    float wD = a * vy1 * vx1;

    int cx0 = min(max(x0, 0), W - 1);
    int cx1 = min(max(x0 + 1, 0), W - 1);
    int cy0 = min(max(y0, 0), H - 1);
    int cy1 = min(max(y0 + 1, 0), H - 1);

    int idx00 = (st + cy0 * W + cx0) * 16;       // in half2 units (row = 16 half2)
    int dX    = (cx1 - cx0) * 16;
    int dY    = (cy1 - cy0) * W * 16;

    // ---- phase B: gather; half-warp hi reads head h, lane li = channel pair ----
    const __half2* vb2 = reinterpret_cast<const __half2*>(g_v_h)
                       + (size_t)(b * HEADS + h) * (NV * 16) + li;
    float accx = 0.f, accy = 0.f;
    const int srcbase = lane & 16;

#pragma unroll
    for (int j = 0; j < 16; j++) {
        int src = srcbase + j;
        float fA = __shfl_sync(0xffffffffu, wA, src);
        float fB = __shfl_sync(0xffffffffu, wB, src);
        float fC = __shfl_sync(0xffffffffu, wC, src);
        float fD = __shfl_sync(0xffffffffu, wD, src);
        int i00  = __shfl_sync(0xffffffffu, idx00, src);
        int dx   = __shfl_sync(0xffffffffu, dX, src);
        int dy   = __shfl_sync(0xffffffffu, dY, src);

        float2 f00 = __half22float2(vb2[i00]);
        float2 f10 = __half22float2(vb2[i00 + dx]);
        float2 f01 = __half22float2(vb2[i00 + dy]);
        float2 f11 = __half22float2(vb2[i00 + dx + dy]);

        accx += fA * f00.x + fB * f10.x + fC * f01.x + fD * f11.x;
        accy += fA * f00.y + fB * f10.y + fC * f01.y + fD * f11.y;
    }

    float2* outp = reinterpret_cast<float2*>(g_att + (size_t)bq * EMBED + h * DIM) + li;
    *outp = make_float2(accx, accy);
}

// ---------------------------------------------------------------------------
extern "C" void kernel_launch(void* const* d_in, const int* in_sizes, int n_in,
                              void* d_out, int out_size)
{
    (void)in_sizes; (void)n_in; (void)out_size;
    const float* query = (const float*)d_in[0];
    const float* value = (const float*)d_in[1];
    const float* qpos  = (const float*)d_in[2];
    const float* ref   = (const float*)d_in[3];
    const float* lro   = (const float*)d_in[4];
    const float* Wv    = (const float*)d_in[6];
    const float* bv    = (const float*)d_in[7];
    const float* Wo    = (const float*)d_in[8];
    const float* bo    = (const float*)d_in[9];
    const float* Wa    = (const float*)d_in[10];
    const float* ba    = (const float*)d_in[11];
    const float* Wout  = (const float*)d_in[12];
    const float* bout  = (const float*)d_in[13];
    float* out = (float*)d_out;

    conv_wv<<<128, 256>>>(Wv);
    {
        dim3 g(2, (BS * NV + 127) / 128);
        gemm_v_bf16<<<g, 256>>>(value, bv, BS * NV);
    }
    {
        dim3 g(3, (BS * NQ + 127) / 128);
        gemm_tc<1><<<g, 256>>>(query, qpos, Wo, Wa, bo, ba, nullptr, nullptr, BS * NQ);
    }
    {
        int total_warps = BS * NQ * 4;
        sample_kernel2<<<(total_warps * 32 + 255) / 256, 256>>>(ref, lro);
    }
    {
        dim3 g(2, (BS * NQ + 127) / 128);
        gemm_tc<2><<<g, 256>>>(nullptr, nullptr, Wout, nullptr, bout, nullptr, query, out, BS * NQ);
    }
}

// round 8
// speedup vs baseline: 3.3118x; 1.2452x over previous
#include <cuda_runtime.h>
#include <cuda_fp16.h>
#include <cuda_bf16.h>
#include <math.h>
#include <stdint.h>

#define HEADS  8
#define LEVELS 4
#define POINTS 4
#define DIM    32
#define EMBED  256
#define NQ     1200
#define BS     8
#define NV     19560   // 92*160 + 46*80 + 23*40 + 12*20

#define OFF_N  256
#define QO_N   384

// Scratch (allocation-free rule: device globals)
__device__ __half    g_v_h[(size_t)BS * HEADS * NV * DIM]; // (b,h,pix,d) fp16 : 80 MB
__device__ float     g_qo[(size_t)BS * NQ * QO_N];         // offsets(256) || logits(128)
__device__ float     g_att[(size_t)BS * NQ * EMBED];
__device__ uint32_t  g_wvT[256 * 128];                     // Wv bf16 pairs [n][kk]

__constant__ int   c_H[4]    = {92, 46, 23, 12};
__constant__ int   c_W[4]    = {160, 80, 40, 20};
__constant__ int   c_start[4]= {0, 14720, 18400, 19320};
__constant__ float c_Hf[4]   = {92.f, 46.f, 23.f, 12.f};
__constant__ float c_Wf[4]   = {160.f, 80.f, 40.f, 20.f};
__constant__ float c_invH[4] = {1.f/92.f, 1.f/46.f, 1.f/23.f, 1.f/12.f};
__constant__ float c_invW[4] = {1.f/160.f, 1.f/80.f, 1.f/40.f, 1.f/20.f};

// ---------------------------------------------------------------------------
__global__ __launch_bounds__(256)
void conv_wv(const float* __restrict__ Wv)
{
    int idx = blockIdx.x * 256 + threadIdx.x;
    int n  = idx >> 7;
    int kk = idx & 127;
    float lo = Wv[(size_t)(2 * kk) * 256 + n];
    float hi = Wv[(size_t)(2 * kk + 1) * 256 + n];
    __nv_bfloat162 p = __floats2bfloat162_rn(lo, hi);
    g_wvT[n * 128 + kk] = *reinterpret_cast<uint32_t*>(&p);
}

// ===========================================================================
// bf16 mma.m16n8k16 value GEMM (R5 single-buffered version — fastest measured)
// 128x128x32 tile, 256 threads (2x4 warps), warp 64x32, register prefetch.
// ===========================================================================
__device__ __forceinline__ void mma_bf16(float& d0, float& d1, float& d2, float& d3,
                                         uint32_t a0, uint32_t a1, uint32_t a2, uint32_t a3,
                                         uint32_t b0, uint32_t b1) {
    asm volatile("mma.sync.aligned.m16n8k16.row.col.f32.bf16.bf16.f32 "
                 "{%0,%1,%2,%3},{%4,%5,%6,%7},{%8,%9},{%0,%1,%2,%3};"
                 : "+f"(d0), "+f"(d1), "+f"(d2), "+f"(d3)
                 : "r"(a0), "r"(a1), "r"(a2), "r"(a3), "r"(b0), "r"(b1));
}

#define PSTRIDE 20   // 16 pairs + 4 pad (uint32)

__global__ __launch_bounds__(256)
void gemm_v_bf16(const float* __restrict__ A, const float* __restrict__ bias, int M)
{
    __shared__ uint32_t As[128][PSTRIDE];   // [m][kpair]
    __shared__ uint32_t Bsm[128][PSTRIDE];  // [n][kpair]

    const int tid  = threadIdx.x;
    const int lane = tid & 31;
    const int warp = tid >> 5;
    const int wm   = warp >> 2;
    const int wn   = warp & 3;
    const int tg   = lane >> 2;
    const int tig  = lane & 3;

    const int block_m = blockIdx.y * 128;
    const int block_n = blockIdx.x * 128;

    float acc[4][4][4];
#pragma unroll
    for (int i = 0; i < 4; i++)
#pragma unroll
        for (int j = 0; j < 4; j++)
#pragma unroll
            for (int r = 0; r < 4; r++) acc[i][j][r] = 0.f;

    float4 aS[4];
    uint4  bU[2];

    const int a_row0 = tid >> 3;
    const int a_c4   = (tid & 7) * 4;
    const int b_n    = tid >> 1;
    const int b_s0   = (tid & 1) * 2;

    auto ldgA = [&](int k0) {
#pragma unroll
        for (int i = 0; i < 4; i++) {
            int gr = block_m + a_row0 + i * 32;
            float4 v = make_float4(0.f, 0.f, 0.f, 0.f);
            if (gr < M)
                v = *reinterpret_cast<const float4*>(A + (size_t)gr * 256 + k0 + a_c4);
            aS[i] = v;
        }
    };
    auto ldgB = [&](int k0) {
        int kk0 = k0 >> 1;
#pragma unroll
        for (int j = 0; j < 2; j++)
            bU[j] = *reinterpret_cast<const uint4*>(
                &g_wvT[(block_n + b_n) * 128 + kk0 + (b_s0 + j) * 4]);
    };
    auto sts = [&]() {
#pragma unroll
        for (int i = 0; i < 4; i++) {
            __nv_bfloat162 p0 = __floats2bfloat162_rn(aS[i].x, aS[i].y);
            __nv_bfloat162 p1 = __floats2bfloat162_rn(aS[i].z, aS[i].w);
            uint2 u;
            u.x = *reinterpret_cast<uint32_t*>(&p0);
            u.y = *reinterpret_cast<uint32_t*>(&p1);
            *reinterpret_cast<uint2*>(&As[a_row0 + i * 32][(a_c4 >> 1)]) = u;
        }
#pragma unroll
        for (int j = 0; j < 2; j++)
            *reinterpret_cast<uint4*>(&Bsm[b_n][(b_s0 + j) * 4]) = bU[j];
    };

    ldgA(0); ldgB(0);

    for (int k0 = 0; k0 < 256; k0 += 32) {
        sts();
        __syncthreads();
        if (k0 + 32 < 256) { ldgA(k0 + 32); ldgB(k0 + 32); }

#pragma unroll
        for (int s = 0; s < 2; s++) {
            const int p0 = s * 8;
            uint32_t a[4][4], b[4][2];
#pragma unroll
            for (int mt = 0; mt < 4; mt++) {
                int m = wm * 64 + mt * 16 + tg;
                a[mt][0] = As[m][p0 + tig];
                a[mt][1] = As[m + 8][p0 + tig];
                a[mt][2] = As[m][p0 + tig + 4];
                a[mt][3] = As[m + 8][p0 + tig + 4];
            }
#pragma unroll
            for (int nt = 0; nt < 4; nt++) {
                int n = wn * 32 + nt * 8 + tg;
                b[nt][0] = Bsm[n][p0 + tig];
                b[nt][1] = Bsm[n][p0 + tig + 4];
            }
#pragma unroll
            for (int mt = 0; mt < 4; mt++)
#pragma unroll
                for (int nt = 0; nt < 4; nt++)
                    mma_bf16(acc[mt][nt][0], acc[mt][nt][1], acc[mt][nt][2], acc[mt][nt][3],
                             a[mt][0], a[mt][1], a[mt][2], a[mt][3],
                             b[nt][0], b[nt][1]);
        }
        __syncthreads();
    }

    // epilogue: scatter fp16 to g_v_h (b, h, pix, d) + bias
#pragma unroll
    for (int mt = 0; mt < 4; mt++) {
#pragma unroll
        for (int nt = 0; nt < 4; nt++) {
            int gc = block_n + wn * 32 + nt * 8 + 2 * tig;
            int h  = gc >> 5;
            int d  = gc & 31;
            float bx = bias[gc], by = bias[gc + 1];
#pragma unroll
            for (int rr = 0; rr < 2; rr++) {
                int gr = block_m + wm * 64 + mt * 16 + tg + rr * 8;
                if (gr >= M) continue;
                int b = gr / NV;
                int n = gr - b * NV;
                size_t oidx = ((size_t)(b * HEADS + h) * NV + n) * DIM + d;
                *reinterpret_cast<__half2*>(g_v_h + oidx) =
                    __floats2half2_rn(acc[mt][nt][rr * 2 + 0] + bx,
                                      acc[mt][nt][rr * 2 + 1] + by);
            }
        }
    }
}

// ===========================================================================
// tf32 mma.sync GEMM for modes 1,2 (unchanged).
// ===========================================================================
__device__ __forceinline__ uint32_t f2tf32(float f) {
    uint32_t u;
    asm("cvt.rna.tf32.f32 %0, %1;" : "=r"(u) : "f"(f));
    return u;
}

__device__ __forceinline__ void mma_tf32(float& d0, float& d1, float& d2, float& d3,
                                         uint32_t a0, uint32_t a1, uint32_t a2, uint32_t a3,
                                         uint32_t b0, uint32_t b1) {
    asm volatile("mma.sync.aligned.m16n8k8.row.col.f32.tf32.tf32.f32 "
                 "{%0,%1,%2,%3},{%4,%5,%6,%7},{%8,%9},{%0,%1,%2,%3};"
                 : "+f"(d0), "+f"(d1), "+f"(d2), "+f"(d3)
                 : "r"(a0), "r"(a1), "r"(a2), "r"(a3), "r"(b0), "r"(b1));
}

#define AS_STRIDE 36
#define BS_STRIDE 136

template <int MODE>
__global__ __launch_bounds__(256)
void gemm_tc(const float* __restrict__ Aext, const float* __restrict__ A2,
             const float* __restrict__ B1,  const float* __restrict__ B2,
             const float* __restrict__ bias1, const float* __restrict__ bias2,
             const float* __restrict__ addsrc, float* __restrict__ Cext, int M)
{
    __shared__ uint32_t As[128][AS_STRIDE];
    __shared__ uint32_t Bsm[32][BS_STRIDE];

    const float* A = (MODE == 2) ? g_att : Aext;

    const int tid  = threadIdx.x;
    const int lane = tid & 31;
    const int warp = tid >> 5;
    const int wm   = warp >> 2;
    const int wn   = warp & 3;
    const int tg   = lane >> 2;
    const int tig  = lane & 3;

    const int block_m = blockIdx.y * 128;
    const int block_n = blockIdx.x * 128;

    float acc[4][4][4];
#pragma unroll
    for (int i = 0; i < 4; i++)
#pragma unroll
        for (int j = 0; j < 4; j++)
#pragma unroll
            for (int r = 0; r < 4; r++) acc[i][j][r] = 0.f;

    float4 aS[4], bS[4];
    const int a_row0 = tid >> 3;
    const int a_c4   = (tid & 7) * 4;
    const int b_k0   = tid >> 5;
    const int b_n4   = lane * 4;

    auto ldgA = [&](int k0) {
#pragma unroll
        for (int i = 0; i < 4; i++) {
            int gr = block_m + a_row0 + i * 32;
            float4 v = make_float4(0.f, 0.f, 0.f, 0.f);
            if (gr < M) {
                v = *reinterpret_cast<const float4*>(A + (size_t)gr * 256 + k0 + a_c4);
                if (MODE == 1) {
                    float4 v2 = *reinterpret_cast<const float4*>(A2 + (size_t)gr * 256 + k0 + a_c4);
                    v.x += v2.x; v.y += v2.y; v.z += v2.z; v.w += v2.w;
                }
            }
            aS[i] = v;
        }
    };
    auto ldgB = [&](int k0) {
#pragma unroll
        for (int i = 0; i < 4; i++) {
            int krow = b_k0 + i * 8;
            int gc   = block_n + b_n4;
            float4 v;
            if (MODE == 1) {
                if (gc < OFF_N) v = *reinterpret_cast<const float4*>(B1 + (size_t)(k0 + krow) * OFF_N + gc);
                else            v = *reinterpret_cast<const float4*>(B2 + (size_t)(k0 + krow) * 128 + (gc - OFF_N));
            } else {
                v = *reinterpret_cast<const float4*>(B1 + (size_t)(k0 + krow) * 256 + gc);
            }
            bS[i] = v;
        }
    };
    auto sts = [&]() {
#pragma unroll
        for (int i = 0; i < 4; i++) {
            uint4 u;
            u.x = f2tf32(aS[i].x); u.y = f2tf32(aS[i].y);
            u.z = f2tf32(aS[i].z); u.w = f2tf32(aS[i].w);
            *reinterpret_cast<uint4*>(&As[a_row0 + i * 32][a_c4]) = u;
        }
#pragma unroll
        for (int i = 0; i < 4; i++) {
            uint4 u;
            u.x = f2tf32(bS[i].x); u.y = f2tf32(bS[i].y);
            u.z = f2tf32(bS[i].z); u.w = f2tf32(bS[i].w);
            *reinterpret_cast<uint4*>(&Bsm[b_k0 + i * 8][b_n4]) = u;
        }
    };

    ldgA(0); ldgB(0);

    for (int k0 = 0; k0 < 256; k0 += 32) {
        sts();
        __syncthreads();
        if (k0 + 32 < 256) { ldgA(k0 + 32); ldgB(k0 + 32); }

#pragma unroll
        for (int ks = 0; ks < 4; ks++) {
            const int k = ks * 8;
            uint32_t a[4][4], b[4][2];
#pragma unroll
            for (int mt = 0; mt < 4; mt++) {
                int m = wm * 64 + mt * 16 + tg;
                a[mt][0] = As[m][k + tig];
                a[mt][1] = As[m + 8][k + tig];
                a[mt][2] = As[m][k + tig + 4];
                a[mt][3] = As[m + 8][k + tig + 4];
            }
#pragma unroll
            for (int nt = 0; nt < 4; nt++) {
                int n = wn * 32 + nt * 8 + tg;
                b[nt][0] = Bsm[k + tig][n];
                b[nt][1] = Bsm[k + tig + 4][n];
            }
#pragma unroll
            for (int mt = 0; mt < 4; mt++)
#pragma unroll
                for (int nt = 0; nt < 4; nt++)
                    mma_tf32(acc[mt][nt][0], acc[mt][nt][1], acc[mt][nt][2], acc[mt][nt][3],
                             a[mt][0], a[mt][1], a[mt][2], a[mt][3],
                             b[nt][0], b[nt][1]);
        }
        __syncthreads();
    }

#pragma unroll
    for (int mt = 0; mt < 4; mt++) {
#pragma unroll
        for (int nt = 0; nt < 4; nt++) {
            int gc = block_n + wn * 32 + nt * 8 + 2 * tig;
            float bx, by;
            if (MODE == 1) {
                bx = (gc < OFF_N) ? bias1[gc] : bias2[gc - OFF_N];
                by = (gc + 1 < OFF_N) ? bias1[gc + 1] : bias2[gc + 1 - OFF_N];
            } else {
                bx = bias1[gc]; by = bias1[gc + 1];
            }
#pragma unroll
            for (int rr = 0; rr < 2; rr++) {
                int gr = block_m + wm * 64 + mt * 16 + tg + rr * 8;
                if (gr >= M) continue;
                float ox = acc[mt][nt][rr * 2 + 0] + bx;
                float oy = acc[mt][nt][rr * 2 + 1] + by;
                if (MODE == 1) {
                    float2 o; o.x = ox; o.y = oy;
                    *reinterpret_cast<float2*>(g_qo + (size_t)gr * QO_N + gc) = o;
                } else {
                    const float2 idv = *reinterpret_cast<const float2*>(addsrc + (size_t)gr * 256 + gc);
                    float2 o; o.x = ox + idv.x; o.y = oy + idv.y;
                    *reinterpret_cast<float2*>(Cext + (size_t)gr * 256 + gc) = o;
                }
            }
        }
    }
}

// ===========================================================================
// Sampling v2 (R6 version — measured 43.4 µs).
// ===========================================================================
__global__ __launch_bounds__(256)
void sample_kernel2(const float* __restrict__ ref, const float* __restrict__ lro)
{
    int gwarp = (blockIdx.x * blockDim.x + threadIdx.x) >> 5;
    int lane  = threadIdx.x & 31;
    int hp    = gwarp & 3;
    int bq    = gwarp >> 2;
    if (bq >= BS * NQ) return;
    int b  = bq / NQ;
    int hi = lane >> 4;
    int li = lane & 15;
    int h  = hp * 2 + hi;

    const float* row = g_qo + (size_t)bq * QO_N;

    float logit = row[OFF_N + h * 16 + li];
    float m = logit;
#pragma unroll
    for (int s = 8; s; s >>= 1) m = fmaxf(m, __shfl_xor_sync(0xffffffffu, m, s));
    float e = expf(logit - m);
    float ss = e;
#pragma unroll
    for (int s = 8; s; s >>= 1) ss += __shfl_xor_sync(0xffffffffu, ss, s);
    float a = e / ss;

    int l = li >> 2;
    int p = li & 3;
    int W = c_W[l], H = c_H[l], st = c_start[l];

    float rx = ref[(size_t)(bq * 4 + l) * 2 + 0];
    float ry = ref[(size_t)(bq * 4 + l) * 2 + 1];
    float lx = lro[(size_t)(bq * 8 + h) * 2 + 0];
    float ly = lro[(size_t)(bq * 8 + h) * 2 + 1];
    float ox = row[((h * 4 + l) * 4 + p) * 2 + 0];
    float oy = row[((h * 4 + l) * 4 + p) * 2 + 1];

    float px = (rx + ox * c_invW[l] + lx) * c_Wf[l] - 0.5f;
    float py = (ry + oy * c_invH[l] + ly) * c_Hf[l] - 0.5f;

    float x0f = floorf(px), y0f = floorf(py);
    int   x0  = (int)x0f,   y0  = (int)y0f;
    float wx1 = px - x0f, wx0 = 1.f - wx1;
    float wy1 = py - y0f, wy0 = 1.f - wy1;

    float vx0 = (x0 >= 0 && x0 < W)         ? wx0 : 0.f;
    float vx1 = (x0 + 1 >= 0 && x0 + 1 < W) ? wx1 : 0.f;
    float vy0 = (y0 >= 0 && y0 < H)         ? wy0 : 0.f;
    float vy1 = (y0 + 1 >= 0 && y0 + 1 < H) ? wy1 : 0.f;

    float wA = a * vy0 * vx0;
    float wB = a * vy0 * vx1;
    float wC = a * vy1 * vx0;
    float wD = a * vy1 * vx1;

    int cx0 = min(max(x0, 0), W - 1);
    int cx1 = min(max(x0 + 1, 0), W - 1);
    int cy0 = min(max(y0, 0), H - 1);
    int cy1 = min(max(y0 + 1, 0), H - 1);

    int idx00 = (st + cy0 * W + cx0) * 16;
    int dX    = (cx1 - cx0) * 16;
    int dY    = (cy1 - cy0) * W * 16;

    const __half2* vb2 = reinterpret_cast<const __half2*>(g_v_h)
                       + (size_t)(b * HEADS + h) * (NV * 16) + li;
    float accx = 0.f, accy = 0.f;
    const int srcbase = lane & 16;

#pragma unroll
    for (int j = 0; j < 16; j++) {
        int src = srcbase + j;
        float fA = __shfl_sync(0xffffffffu, wA, src);
        float fB = __shfl_sync(0xffffffffu, wB, src);
        float fC = __shfl_sync(0xffffffffu, wC, src);
        float fD = __shfl_sync(0xffffffffu, wD, src);
        int i00  = __shfl_sync(0xffffffffu, idx00, src);
        int dx   = __shfl_sync(0xffffffffu, dX, src);
        int dy   = __shfl_sync(0xffffffffu, dY, src);

        float2 f00 = __half22float2(vb2[i00]);
        float2 f10 = __half22float2(vb2[i00 + dx]);
        float2 f01 = __half22float2(vb2[i00 + dy]);
        float2 f11 = __half22float2(vb2[i00 + dx + dy]);

        accx += fA * f00.x + fB * f10.x + fC * f01.x + fD * f11.x;
        accy += fA * f00.y + fB * f10.y + fC * f01.y + fD * f11.y;
    }

    float2* outp = reinterpret_cast<float2*>(g_att + (size_t)bq * EMBED + h * DIM) + li;
    *outp = make_float2(accx, accy);
}

// ---------------------------------------------------------------------------
extern "C" void kernel_launch(void* const* d_in, const int* in_sizes, int n_in,
                              void* d_out, int out_size)
{
    (void)in_sizes; (void)n_in; (void)out_size;
    const float* query = (const float*)d_in[0];
    const float* value = (const float*)d_in[1];
    const float* qpos  = (const float*)d_in[2];
    const float* ref   = (const float*)d_in[3];
    const float* lro   = (const float*)d_in[4];
    const float* Wv    = (const float*)d_in[6];
    const float* bv    = (const float*)d_in[7];
    const float* Wo    = (const float*)d_in[8];
    const float* bo    = (const float*)d_in[9];
    const float* Wa    = (const float*)d_in[10];
    const float* ba    = (const float*)d_in[11];
    const float* Wout  = (const float*)d_in[12];
    const float* bout  = (const float*)d_in[13];
    float* out = (float*)d_out;

    conv_wv<<<128, 256>>>(Wv);
    {
        dim3 g(2, (BS * NV + 127) / 128);
        gemm_v_bf16<<<g, 256>>>(value, bv, BS * NV);
    }
    {
        dim3 g(3, (BS * NQ + 127) / 128);
        gemm_tc<1><<<g, 256>>>(query, qpos, Wo, Wa, bo, ba, nullptr, nullptr, BS * NQ);
    }
    {
        int total_warps = BS * NQ * 4;
        sample_kernel2<<<(total_warps * 32 + 255) / 256, 256>>>(ref, lro);
    }
    {
        dim3 g(2, (BS * NQ + 127) / 128);
        gemm_tc<2><<<g, 256>>>(nullptr, nullptr, Wout, nullptr, bout, nullptr, query, out, BS * NQ);
    }
}

// round 9
// speedup vs baseline: 3.3440x; 1.0097x over previous
#include <cuda_runtime.h>
#include <cuda_fp16.h>
#include <cuda_bf16.h>
#include <math.h>
#include <stdint.h>

#define HEADS  8
#define LEVELS 4
#define POINTS 4
#define DIM    32
#define EMBED  256
#define NQ     1200
#define BS     8
#define NV     19560   // 92*160 + 46*80 + 23*40 + 12*20

#define OFF_N  256
#define QO_N   384

// Scratch (allocation-free rule: device globals)
__device__ __half    g_v_h[(size_t)BS * HEADS * NV * DIM]; // (b,h,pix,d) fp16 : 80 MB
__device__ float     g_qo[(size_t)BS * NQ * QO_N];         // offsets(256) || logits(128)
__device__ float     g_att[(size_t)BS * NQ * EMBED];
__device__ uint32_t  g_wvT[256 * 128];                     // Wv bf16 pairs [n][kk]

__constant__ int   c_H[4]    = {92, 46, 23, 12};
__constant__ int   c_W[4]    = {160, 80, 40, 20};
__constant__ int   c_start[4]= {0, 14720, 18400, 19320};
__constant__ float c_Hf[4]   = {92.f, 46.f, 23.f, 12.f};
__constant__ float c_Wf[4]   = {160.f, 80.f, 40.f, 20.f};
__constant__ float c_invH[4] = {1.f/92.f, 1.f/46.f, 1.f/23.f, 1.f/12.f};
__constant__ float c_invW[4] = {1.f/160.f, 1.f/80.f, 1.f/40.f, 1.f/20.f};

// ---------------------------------------------------------------------------
__global__ __launch_bounds__(256)
void conv_wv(const float* __restrict__ Wv)
{
    int idx = blockIdx.x * 256 + threadIdx.x;
    int n  = idx >> 7;
    int kk = idx & 127;
    float lo = Wv[(size_t)(2 * kk) * 256 + n];
    float hi = Wv[(size_t)(2 * kk + 1) * 256 + n];
    __nv_bfloat162 p = __floats2bfloat162_rn(lo, hi);
    g_wvT[n * 128 + kk] = *reinterpret_cast<uint32_t*>(&p);
}

// ===========================================================================
// bf16 mma.m16n8k16 value GEMM with ldmatrix.x4 fragment loads.
// 128x128x32 tile, 256 threads (2x4 warps), warp 64x32, register prefetch.
// ===========================================================================
__device__ __forceinline__ void mma_bf16(float& d0, float& d1, float& d2, float& d3,
                                         uint32_t a0, uint32_t a1, uint32_t a2, uint32_t a3,
                                         uint32_t b0, uint32_t b1) {
    asm volatile("mma.sync.aligned.m16n8k16.row.col.f32.bf16.bf16.f32 "
                 "{%0,%1,%2,%3},{%4,%5,%6,%7},{%8,%9},{%0,%1,%2,%3};"
                 : "+f"(d0), "+f"(d1), "+f"(d2), "+f"(d3)
                 : "r"(a0), "r"(a1), "r"(a2), "r"(a3), "r"(b0), "r"(b1));
}

__device__ __forceinline__ void ldsm_x4(uint32_t& r0, uint32_t& r1, uint32_t& r2, uint32_t& r3,
                                        uint32_t addr) {
    asm volatile("ldmatrix.sync.aligned.m8n8.x4.shared.b16 {%0,%1,%2,%3}, [%4];"
                 : "=r"(r0), "=r"(r1), "=r"(r2), "=r"(r3) : "r"(addr));
}

__device__ __forceinline__ uint32_t smem_u32(const void* p) {
    uint32_t a;
    asm("{ .reg .u64 t; cvta.to.shared.u64 t, %1; cvt.u32.u64 %0, t; }" : "=r"(a) : "l"(p));
    return a;
}

#define PSTRIDE 20   // 16 kpairs + 4 pad (uint32): ldmatrix phases conflict-free

__global__ __launch_bounds__(256)
void gemm_v_bf16(const float* __restrict__ A, const float* __restrict__ bias, int M)
{
    __shared__ uint32_t As[128][PSTRIDE];   // [m][kpair]
    __shared__ uint32_t Bsm[128][PSTRIDE];  // [n][kpair]

    const int tid  = threadIdx.x;
    const int lane = tid & 31;
    const int warp = tid >> 5;
    const int wm   = warp >> 2;
    const int wn   = warp & 3;
    const int tg   = lane >> 2;
    const int tig  = lane & 3;

    const int block_m = blockIdx.y * 128;
    const int block_n = blockIdx.x * 128;

    float acc[4][4][4];
#pragma unroll
    for (int i = 0; i < 4; i++)
#pragma unroll
        for (int j = 0; j < 4; j++)
#pragma unroll
            for (int r = 0; r < 4; r++) acc[i][j][r] = 0.f;

    float4 aS[4];
    uint4  bU[2];

    const int a_row0 = tid >> 3;
    const int a_c4   = (tid & 7) * 4;
    const int b_n    = tid >> 1;
    const int b_s0   = (tid & 1) * 2;

    // ldmatrix per-lane addresses (byte addresses into shared)
    // A fragment mt: row = wm*64 + mt*16 + (lane&15), pairoff = (lane>>4)*4
    uint32_t aAddr[4];
    {
        uint32_t base = smem_u32(As);
        int row = wm * 64 + (lane & 15);
        int po  = (lane >> 4) * 4;
#pragma unroll
        for (int mt = 0; mt < 4; mt++)
            aAddr[mt] = base + (uint32_t)(((row + mt * 16) * PSTRIDE + po) * 4);
    }
    // B group g (covers nt=2g,2g+1): row = wn*32 + g*16 + (lane&7) + ((lane>>4)&1)*8,
    // pairoff = ((lane>>3)&1)*4
    uint32_t bAddr[2];
    {
        uint32_t base = smem_u32(Bsm);
        int row = wn * 32 + (lane & 7) + ((lane >> 4) & 1) * 8;
        int po  = ((lane >> 3) & 1) * 4;
#pragma unroll
        for (int g = 0; g < 2; g++)
            bAddr[g] = base + (uint32_t)(((row + g * 16) * PSTRIDE + po) * 4);
    }

    auto ldgA = [&](int k0) {
#pragma unroll
        for (int i = 0; i < 4; i++) {
            int gr = block_m + a_row0 + i * 32;
            float4 v = make_float4(0.f, 0.f, 0.f, 0.f);
            if (gr < M)
                v = *reinterpret_cast<const float4*>(A + (size_t)gr * 256 + k0 + a_c4);
            aS[i] = v;
        }
    };
    auto ldgB = [&](int k0) {
        int kk0 = k0 >> 1;
#pragma unroll
        for (int j = 0; j < 2; j++)
            bU[j] = *reinterpret_cast<const uint4*>(
                &g_wvT[(block_n + b_n) * 128 + kk0 + (b_s0 + j) * 4]);
    };
    auto sts = [&]() {
#pragma unroll
        for (int i = 0; i < 4; i++) {
            __nv_bfloat162 p0 = __floats2bfloat162_rn(aS[i].x, aS[i].y);
            __nv_bfloat162 p1 = __floats2bfloat162_rn(aS[i].z, aS[i].w);
            uint2 u;
            u.x = *reinterpret_cast<uint32_t*>(&p0);
            u.y = *reinterpret_cast<uint32_t*>(&p1);
            *reinterpret_cast<uint2*>(&As[a_row0 + i * 32][(a_c4 >> 1)]) = u;
        }
#pragma unroll
        for (int j = 0; j < 2; j++)
            *reinterpret_cast<uint4*>(&Bsm[b_n][(b_s0 + j) * 4]) = bU[j];
    };

    ldgA(0); ldgB(0);

    for (int k0 = 0; k0 < 256; k0 += 32) {
        sts();
        __syncthreads();
        if (k0 + 32 < 256) { ldgA(k0 + 32); ldgB(k0 + 32); }

#pragma unroll
        for (int s = 0; s < 2; s++) {
            const uint32_t soff = (uint32_t)(s * 32);  // 8 kpairs = 32 bytes
            uint32_t a[4][4], b[4][2];
#pragma unroll
            for (int mt = 0; mt < 4; mt++)
                ldsm_x4(a[mt][0], a[mt][1], a[mt][2], a[mt][3], aAddr[mt] + soff);
#pragma unroll
            for (int g = 0; g < 2; g++)
                ldsm_x4(b[2 * g][0], b[2 * g][1], b[2 * g + 1][0], b[2 * g + 1][1],
                        bAddr[g] + soff);
#pragma unroll
            for (int mt = 0; mt < 4; mt++)
#pragma unroll
                for (int nt = 0; nt < 4; nt++)
                    mma_bf16(acc[mt][nt][0], acc[mt][nt][1], acc[mt][nt][2], acc[mt][nt][3],
                             a[mt][0], a[mt][1], a[mt][2], a[mt][3],
                             b[nt][0], b[nt][1]);
        }
        __syncthreads();
    }

    // epilogue: scatter fp16 to g_v_h (b, h, pix, d) + bias
#pragma unroll
    for (int mt = 0; mt < 4; mt++) {
#pragma unroll
        for (int nt = 0; nt < 4; nt++) {
            int gc = block_n + wn * 32 + nt * 8 + 2 * tig;
            int h  = gc >> 5;
            int d  = gc & 31;
            float bx = bias[gc], by = bias[gc + 1];
#pragma unroll
            for (int rr = 0; rr < 2; rr++) {
                int gr = block_m + wm * 64 + mt * 16 + tg + rr * 8;
                if (gr >= M) continue;
                int b = gr / NV;
                int n = gr - b * NV;
                size_t oidx = ((size_t)(b * HEADS + h) * NV + n) * DIM + d;
                *reinterpret_cast<__half2*>(g_v_h + oidx) =
                    __floats2half2_rn(acc[mt][nt][rr * 2 + 0] + bx,
                                      acc[mt][nt][rr * 2 + 1] + by);
            }
        }
    }
}

// ===========================================================================
// tf32 mma.sync GEMM for modes 1,2 (unchanged).
// ===========================================================================
__device__ __forceinline__ uint32_t f2tf32(float f) {
    uint32_t u;
    asm("cvt.rna.tf32.f32 %0, %1;" : "=r"(u) : "f"(f));
    return u;
}

__device__ __forceinline__ void mma_tf32(float& d0, float& d1, float& d2, float& d3,
                                         uint32_t a0, uint32_t a1, uint32_t a2, uint32_t a3,
                                         uint32_t b0, uint32_t b1) {
    asm volatile("mma.sync.aligned.m16n8k8.row.col.f32.tf32.tf32.f32 "
                 "{%0,%1,%2,%3},{%4,%5,%6,%7},{%8,%9},{%0,%1,%2,%3};"
                 : "+f"(d0), "+f"(d1), "+f"(d2), "+f"(d3)
                 : "r"(a0), "r"(a1), "r"(a2), "r"(a3), "r"(b0), "r"(b1));
}

#define AS_STRIDE 36
#define BS_STRIDE 136

template <int MODE>
__global__ __launch_bounds__(256)
void gemm_tc(const float* __restrict__ Aext, const float* __restrict__ A2,
             const float* __restrict__ B1,  const float* __restrict__ B2,
             const float* __restrict__ bias1, const float* __restrict__ bias2,
             const float* __restrict__ addsrc, float* __restrict__ Cext, int M)
{
    __shared__ uint32_t As[128][AS_STRIDE];
    __shared__ uint32_t Bsm[32][BS_STRIDE];

    const float* A = (MODE == 2) ? g_att : Aext;

    const int tid  = threadIdx.x;
    const int lane = tid & 31;
    const int warp = tid >> 5;
    const int wm   = warp >> 2;
    const int wn   = warp & 3;
    const int tg   = lane >> 2;
    const int tig  = lane & 3;

    const int block_m = blockIdx.y * 128;
    const int block_n = blockIdx.x * 128;

    float acc[4][4][4];
#pragma unroll
    for (int i = 0; i < 4; i++)
#pragma unroll
        for (int j = 0; j < 4; j++)
#pragma unroll
            for (int r = 0; r < 4; r++) acc[i][j][r] = 0.f;

    float4 aS[4], bS[4];
    const int a_row0 = tid >> 3;
    const int a_c4   = (tid & 7) * 4;
    const int b_k0   = tid >> 5;
    const int b_n4   = lane * 4;

    auto ldgA = [&](int k0) {
#pragma unroll
        for (int i = 0; i < 4; i++) {
            int gr = block_m + a_row0 + i * 32;
            float4 v = make_float4(0.f, 0.f, 0.f, 0.f);
            if (gr < M) {
                v = *reinterpret_cast<const float4*>(A + (size_t)gr * 256 + k0 + a_c4);
                if (MODE == 1) {
                    float4 v2 = *reinterpret_cast<const float4*>(A2 + (size_t)gr * 256 + k0 + a_c4);
                    v.x += v2.x; v.y += v2.y; v.z += v2.z; v.w += v2.w;
                }
            }
            aS[i] = v;
        }
    };
    auto ldgB = [&](int k0) {
#pragma unroll
        for (int i = 0; i < 4; i++) {
            int krow = b_k0 + i * 8;
            int gc   = block_n + b_n4;
            float4 v;
            if (MODE == 1) {
                if (gc < OFF_N) v = *reinterpret_cast<const float4*>(B1 + (size_t)(k0 + krow) * OFF_N + gc);
                else            v = *reinterpret_cast<const float4*>(B2 + (size_t)(k0 + krow) * 128 + (gc - OFF_N));
            } else {
                v = *reinterpret_cast<const float4*>(B1 + (size_t)(k0 + krow) * 256 + gc);
            }
            bS[i] = v;
        }
    };
    auto sts = [&]() {
#pragma unroll
        for (int i = 0; i < 4; i++) {
            uint4 u;
            u.x = f2tf32(aS[i].x); u.y = f2tf32(aS[i].y);
            u.z = f2tf32(aS[i].z); u.w = f2tf32(aS[i].w);
            *reinterpret_cast<uint4*>(&As[a_row0 + i * 32][a_c4]) = u;
        }
#pragma unroll
        for (int i = 0; i < 4; i++) {
            uint4 u;
            u.x = f2tf32(bS[i].x); u.y = f2tf32(bS[i].y);
            u.z = f2tf32(bS[i].z); u.w = f2tf32(bS[i].w);
            *reinterpret_cast<uint4*>(&Bsm[b_k0 + i * 8][b_n4]) = u;
        }
    };

    ldgA(0); ldgB(0);

    for (int k0 = 0; k0 < 256; k0 += 32) {
        sts();
        __syncthreads();
        if (k0 + 32 < 256) { ldgA(k0 + 32); ldgB(k0 + 32); }

#pragma unroll
        for (int ks = 0; ks < 4; ks++) {
            const int k = ks * 8;
            uint32_t a[4][4], b[4][2];
#pragma unroll
            for (int mt = 0; mt < 4; mt++) {
                int m = wm * 64 + mt * 16 + tg;
                a[mt][0] = As[m][k + tig];
                a[mt][1] = As[m + 8][k + tig];
                a[mt][2] = As[m][k + tig + 4];
                a[mt][3] = As[m + 8][k + tig + 4];
            }
#pragma unroll
            for (int nt = 0; nt < 4; nt++) {
                int n = wn * 32 + nt * 8 + tg;
                b[nt][0] = Bsm[k + tig][n];
                b[nt][1] = Bsm[k + tig + 4][n];
            }
#pragma unroll
            for (int mt = 0; mt < 4; mt++)
#pragma unroll
                for (int nt = 0; nt < 4; nt++)
                    mma_tf32(acc[mt][nt][0], acc[mt][nt][1], acc[mt][nt][2], acc[mt][nt][3],
                             a[mt][0], a[mt][1], a[mt][2], a[mt][3],
                             b[nt][0], b[nt][1]);
        }
        __syncthreads();
    }

#pragma unroll
    for (int mt = 0; mt < 4; mt++) {
#pragma unroll
        for (int nt = 0; nt < 4; nt++) {
            int gc = block_n + wn * 32 + nt * 8 + 2 * tig;
            float bx, by;
            if (MODE == 1) {
                bx = (gc < OFF_N) ? bias1[gc] : bias2[gc - OFF_N];
                by = (gc + 1 < OFF_N) ? bias1[gc + 1] : bias2[gc + 1 - OFF_N];
            } else {
                bx = bias1[gc]; by = bias1[gc + 1];
            }
#pragma unroll
            for (int rr = 0; rr < 2; rr++) {
                int gr = block_m + wm * 64 + mt * 16 + tg + rr * 8;
                if (gr >= M) continue;
                float ox = acc[mt][nt][rr * 2 + 0] + bx;
                float oy = acc[mt][nt][rr * 2 + 1] + by;
                if (MODE == 1) {
                    float2 o; o.x = ox; o.y = oy;
                    *reinterpret_cast<float2*>(g_qo + (size_t)gr * QO_N + gc) = o;
                } else {
                    const float2 idv = *reinterpret_cast<const float2*>(addsrc + (size_t)gr * 256 + gc);
                    float2 o; o.x = ox + idv.x; o.y = oy + idv.y;
                    *reinterpret_cast<float2*>(Cext + (size_t)gr * 256 + gc) = o;
                }
            }
        }
    }
}

// ===========================================================================
// Sampling v3: packed broadcasts (3 shuffles/point instead of 7).
// One warp = (b,q,head-pair); half-warp hi = head, lane-in-half li = point.
// ===========================================================================
__global__ __launch_bounds__(256)
void sample_kernel3(const float* __restrict__ ref, const float* __restrict__ lro)
{
    int gwarp = (blockIdx.x * blockDim.x + threadIdx.x) >> 5;
    int lane  = threadIdx.x & 31;
    int hp    = gwarp & 3;
    int bq    = gwarp >> 2;
    if (bq >= BS * NQ) return;
    int b  = bq / NQ;
    int hi = lane >> 4;
    int li = lane & 15;
    int h  = hp * 2 + hi;

    const float* row = g_qo + (size_t)bq * QO_N;

    // softmax over 16 logits, per half-warp
    float logit = row[OFF_N + h * 16 + li];
    float m = logit;
#pragma unroll
    for (int s = 8; s; s >>= 1) m = fmaxf(m, __shfl_xor_sync(0xffffffffu, m, s));
    float e = expf(logit - m);
    float ss = e;
#pragma unroll
    for (int s = 8; s; s >>= 1) ss += __shfl_xor_sync(0xffffffffu, ss, s);
    float a = e / ss;

    // phase A: per-lane point params
    int l = li >> 2;
    int p = li & 3;
    int W = c_W[l], H = c_H[l], st = c_start[l];

    float rx = ref[(size_t)(bq * 4 + l) * 2 + 0];
    float ry = ref[(size_t)(bq * 4 + l) * 2 + 1];
    float lx = lro[(size_t)(bq * 8 + h) * 2 + 0];
    float ly = lro[(size_t)(bq * 8 + h) * 2 + 1];
    float ox = row[((h * 4 + l) * 4 + p) * 2 + 0];
    float oy = row[((h * 4 + l) * 4 + p) * 2 + 1];

    float px = (rx + ox * c_invW[l] + lx) * c_Wf[l] - 0.5f;
    float py = (ry + oy * c_invH[l] + ly) * c_Hf[l] - 0.5f;

    float x0f = floorf(px), y0f = floorf(py);
    int   x0  = (int)x0f,   y0  = (int)y0f;
    float wx1 = px - x0f, wx0 = 1.f - wx1;
    float wy1 = py - y0f, wy0 = 1.f - wy1;

    float vx0 = (x0 >= 0 && x0 < W)         ? wx0 : 0.f;
    float vx1 = (x0 + 1 >= 0 && x0 + 1 < W) ? wx1 : 0.f;
    float vy0 = (y0 >= 0 && y0 < H)         ? wy0 : 0.f;
    float vy1 = (y0 + 1 >= 0 && y0 + 1 < H) ? wy1 : 0.f;

    // attention-premultiplied corner weights, packed fp16
    __half2 hAB = __floats2half2_rn(a * vy0 * vx0, a * vy0 * vx1);
    __half2 hCD = __floats2half2_rn(a * vy1 * vx0, a * vy1 * vx1);
    uint32_t uAB = *reinterpret_cast<uint32_t*>(&hAB);
    uint32_t uCD = *reinterpret_cast<uint32_t*>(&hCD);

    int cx0 = min(max(x0, 0), W - 1);
    int cx1 = min(max(x0 + 1, 0), W - 1);
    int cy0 = min(max(y0, 0), H - 1);
    int cy1 = min(max(y0 + 1, 0), H - 1);

    // packed index: bits 0..18 = base index (half2 units), bit 20 = dx flag, 21 = dy flag
    int idxPack = (st + cy0 * W + cx0) * 16
                | ((cx1 - cx0) << 20)
                | ((cy1 - cy0) << 21);

    const __half2* vb2 = reinterpret_cast<const __half2*>(g_v_h)
                       + (size_t)(b * HEADS + h) * (NV * 16) + li;
    float accx = 0.f, accy = 0.f;
    const int srcbase = lane & 16;
    const int Wtab16[4] = {160 * 16, 80 * 16, 40 * 16, 20 * 16};

#pragma unroll
    for (int j = 0; j < 16; j++) {
        int src = srcbase + j;
        uint32_t pAB = __shfl_sync(0xffffffffu, uAB, src);
        uint32_t pCD = __shfl_sync(0xffffffffu, uCD, src);
        int      pk  = __shfl_sync(0xffffffffu, idxPack, src);

        int i00 = pk & 0xFFFFF;
        int dx  = ((pk >> 20) & 1) * 16;
        int dy  = ((pk >> 21) & 1) * Wtab16[j >> 2];   // compile-time W per unrolled j

        float2 wab = __half22float2(*reinterpret_cast<const __half2*>(&pAB));
        float2 wcd = __half22float2(*reinterpret_cast<const __half2*>(&pCD));

        float2 f00 = __half22float2(vb2[i00]);
        float2 f10 = __half22float2(vb2[i00 + dx]);
        float2 f01 = __half22float2(vb2[i00 + dy]);
        float2 f11 = __half22float2(vb2[i00 + dx + dy]);

        accx += wab.x * f00.x + wab.y * f10.x + wcd.x * f01.x + wcd.y * f11.x;
        accy += wab.x * f00.y + wab.y * f10.y + wcd.x * f01.y + wcd.y * f11.y;
    }

    float2* outp = reinterpret_cast<float2*>(g_att + (size_t)bq * EMBED + h * DIM) + li;
    *outp = make_float2(accx, accy);
}

// ---------------------------------------------------------------------------
extern "C" void kernel_launch(void* const* d_in, const int* in_sizes, int n_in,
                              void* d_out, int out_size)
{
    (void)in_sizes; (void)n_in; (void)out_size;
    const float* query = (const float*)d_in[0];
    const float* value = (const float*)d_in[1];
    const float* qpos  = (const float*)d_in[2];
    const float* ref   = (const float*)d_in[3];
    const float* lro   = (const float*)d_in[4];
    const float* Wv    = (const float*)d_in[6];
    const float* bv    = (const float*)d_in[7];
    const float* Wo    = (const float*)d_in[8];
    const float* bo    = (const float*)d_in[9];
    const float* Wa    = (const float*)d_in[10];
    const float* ba    = (const float*)d_in[11];
    const float* Wout  = (const float*)d_in[12];
    const float* bout  = (const float*)d_in[13];
    float* out = (float*)d_out;

    conv_wv<<<128, 256>>>(Wv);
    {
        dim3 g(2, (BS * NV + 127) / 128);
        gemm_v_bf16<<<g, 256>>>(value, bv, BS * NV);
    }
    {
        dim3 g(3, (BS * NQ + 127) / 128);
        gemm_tc<1><<<g, 256>>>(query, qpos, Wo, Wa, bo, ba, nullptr, nullptr, BS * NQ);
    }
    {
        int total_warps = BS * NQ * 4;
        sample_kernel3<<<(total_warps * 32 + 255) / 256, 256>>>(ref, lro);
    }
    {
        dim3 g(2, (BS * NQ + 127) / 128);
        gemm_tc<2><<<g, 256>>>(nullptr, nullptr, Wout, nullptr, bout, nullptr, query, out, BS * NQ);
    }
}

// round 10
// speedup vs baseline: 3.5444x; 1.0599x over previous
#include <cuda_runtime.h>
#include <cuda_fp16.h>
#include <cuda_bf16.h>
#include <math.h>
#include <stdint.h>

#define HEADS  8
#define LEVELS 4
#define POINTS 4
#define DIM    32
#define EMBED  256
#define NQ     1200
#define BS     8
#define NV     19560   // 92*160 + 46*80 + 23*40 + 12*20

#define OFF_N  256
#define QO_N   384

// Scratch (allocation-free rule: device globals)
__device__ __half    g_v_h[(size_t)BS * HEADS * NV * DIM]; // (b,h,pix,d) fp16 : 80 MB
__device__ float     g_qo[(size_t)BS * NQ * QO_N];         // offsets(256) || logits(128)
__device__ float     g_att[(size_t)BS * NQ * EMBED];
__device__ uint32_t  g_wvT[256 * 128];                     // Wv bf16 pairs [n][kk]

__constant__ int   c_H[4]    = {92, 46, 23, 12};
__constant__ int   c_W[4]    = {160, 80, 40, 20};
__constant__ int   c_start[4]= {0, 14720, 18400, 19320};
__constant__ float c_Hf[4]   = {92.f, 46.f, 23.f, 12.f};
__constant__ float c_Wf[4]   = {160.f, 80.f, 40.f, 20.f};
__constant__ float c_invH[4] = {1.f/92.f, 1.f/46.f, 1.f/23.f, 1.f/12.f};
__constant__ float c_invW[4] = {1.f/160.f, 1.f/80.f, 1.f/40.f, 1.f/20.f};

// ---------------------------------------------------------------------------
__global__ __launch_bounds__(256)
void conv_wv(const float* __restrict__ Wv)
{
    int idx = blockIdx.x * 256 + threadIdx.x;
    int n  = idx >> 7;
    int kk = idx & 127;
    float lo = Wv[(size_t)(2 * kk) * 256 + n];
    float hi = Wv[(size_t)(2 * kk + 1) * 256 + n];
    __nv_bfloat162 p = __floats2bfloat162_rn(lo, hi);
    g_wvT[n * 128 + kk] = *reinterpret_cast<uint32_t*>(&p);
}

// ===========================================================================
// bf16 mma.m16n8k16 value GEMM with ldmatrix loads and COALESCED epilogue
// (smem-staged: per-warp 16x32-half tiles -> full 64B pixel-row STG.128).
// ===========================================================================
__device__ __forceinline__ void mma_bf16(float& d0, float& d1, float& d2, float& d3,
                                         uint32_t a0, uint32_t a1, uint32_t a2, uint32_t a3,
                                         uint32_t b0, uint32_t b1) {
    asm volatile("mma.sync.aligned.m16n8k16.row.col.f32.bf16.bf16.f32 "
                 "{%0,%1,%2,%3},{%4,%5,%6,%7},{%8,%9},{%0,%1,%2,%3};"
                 : "+f"(d0), "+f"(d1), "+f"(d2), "+f"(d3)
                 : "r"(a0), "r"(a1), "r"(a2), "r"(a3), "r"(b0), "r"(b1));
}

__device__ __forceinline__ void ldsm_x4(uint32_t& r0, uint32_t& r1, uint32_t& r2, uint32_t& r3,
                                        uint32_t addr) {
    asm volatile("ldmatrix.sync.aligned.m8n8.x4.shared.b16 {%0,%1,%2,%3}, [%4];"
                 : "=r"(r0), "=r"(r1), "=r"(r2), "=r"(r3) : "r"(addr));
}

__device__ __forceinline__ uint32_t smem_u32(const void* p) {
    uint32_t a;
    asm("{ .reg .u64 t; cvta.to.shared.u64 t, %1; cvt.u32.u64 %0, t; }" : "=r"(a) : "l"(p));
    return a;
}

#define PSTRIDE 20   // 16 kpairs + 4 pad (uint32)
#define STG_ROW 40   // staging row stride in halves (bank-conflict-free)

__global__ __launch_bounds__(256)
void gemm_v_bf16(const float* __restrict__ A, const float* __restrict__ bias, int M)
{
    __shared__ uint32_t As[128][PSTRIDE];   // [m][kpair]; reused as epilogue staging
    __shared__ uint32_t Bsm[128][PSTRIDE];  // [n][kpair]

    const int tid  = threadIdx.x;
    const int lane = tid & 31;
    const int warp = tid >> 5;
    const int wm   = warp >> 2;
    const int wn   = warp & 3;
    const int tg   = lane >> 2;
    const int tig  = lane & 3;

    const int block_m = blockIdx.y * 128;
    const int block_n = blockIdx.x * 128;

    float acc[4][4][4];
#pragma unroll
    for (int i = 0; i < 4; i++)
#pragma unroll
        for (int j = 0; j < 4; j++)
#pragma unroll
            for (int r = 0; r < 4; r++) acc[i][j][r] = 0.f;

    float4 aS[4];
    uint4  bU[2];

    const int a_row0 = tid >> 3;
    const int a_c4   = (tid & 7) * 4;
    const int b_n    = tid >> 1;
    const int b_s0   = (tid & 1) * 2;

    uint32_t aAddr[4];
    {
        uint32_t base = smem_u32(As);
        int row = wm * 64 + (lane & 15);
        int po  = (lane >> 4) * 4;
#pragma unroll
        for (int mt = 0; mt < 4; mt++)
            aAddr[mt] = base + (uint32_t)(((row + mt * 16) * PSTRIDE + po) * 4);
    }
    uint32_t bAddr[2];
    {
        uint32_t base = smem_u32(Bsm);
        int row = wn * 32 + (lane & 7) + ((lane >> 4) & 1) * 8;
        int po  = ((lane >> 3) & 1) * 4;
#pragma unroll
        for (int g = 0; g < 2; g++)
            bAddr[g] = base + (uint32_t)(((row + g * 16) * PSTRIDE + po) * 4);
    }

    auto ldgA = [&](int k0) {
#pragma unroll
        for (int i = 0; i < 4; i++) {
            int gr = block_m + a_row0 + i * 32;
            float4 v = make_float4(0.f, 0.f, 0.f, 0.f);
            if (gr < M)
                v = *reinterpret_cast<const float4*>(A + (size_t)gr * 256 + k0 + a_c4);
            aS[i] = v;
        }
    };
    auto ldgB = [&](int k0) {
        int kk0 = k0 >> 1;
#pragma unroll
        for (int j = 0; j < 2; j++)
            bU[j] = *reinterpret_cast<const uint4*>(
                &g_wvT[(block_n + b_n) * 128 + kk0 + (b_s0 + j) * 4]);
    };
    auto sts = [&]() {
#pragma unroll
        for (int i = 0; i < 4; i++) {
            __nv_bfloat162 p0 = __floats2bfloat162_rn(aS[i].x, aS[i].y);
            __nv_bfloat162 p1 = __floats2bfloat162_rn(aS[i].z, aS[i].w);
            uint2 u;
            u.x = *reinterpret_cast<uint32_t*>(&p0);
            u.y = *reinterpret_cast<uint32_t*>(&p1);
            *reinterpret_cast<uint2*>(&As[a_row0 + i * 32][(a_c4 >> 1)]) = u;
        }
#pragma unroll
        for (int j = 0; j < 2; j++)
            *reinterpret_cast<uint4*>(&Bsm[b_n][(b_s0 + j) * 4]) = bU[j];
    };

    ldgA(0); ldgB(0);

    for (int k0 = 0; k0 < 256; k0 += 32) {
        sts();
        __syncthreads();
        if (k0 + 32 < 256) { ldgA(k0 + 32); ldgB(k0 + 32); }

#pragma unroll
        for (int s = 0; s < 2; s++) {
            const uint32_t soff = (uint32_t)(s * 32);
            uint32_t a[4][4], b[4][2];
#pragma unroll
            for (int mt = 0; mt < 4; mt++)
                ldsm_x4(a[mt][0], a[mt][1], a[mt][2], a[mt][3], aAddr[mt] + soff);
#pragma unroll
            for (int g = 0; g < 2; g++)
                ldsm_x4(b[2 * g][0], b[2 * g][1], b[2 * g + 1][0], b[2 * g + 1][1],
                        bAddr[g] + soff);
#pragma unroll
            for (int mt = 0; mt < 4; mt++)
#pragma unroll
                for (int nt = 0; nt < 4; nt++)
                    mma_bf16(acc[mt][nt][0], acc[mt][nt][1], acc[mt][nt][2], acc[mt][nt][3],
                             a[mt][0], a[mt][1], a[mt][2], a[mt][3],
                             b[nt][0], b[nt][1]);
        }
        __syncthreads();
    }

    // ===== coalesced epilogue =====
    // Each warp owns rows [wm*64, +64) of ONE head (head = 4*blockIdx.x + wn).
    // Stage 16 rows x 32 halves in smem (row stride 40 halves), then write
    // full 64B pixel rows with STG.128 (4 lanes per row).
    const int head = 4 * blockIdx.x + wn;
    __half* stg = reinterpret_cast<__half*>(As) + warp * (16 * STG_ROW);
    const float bx[4] = { bias[head * 32 + 0 * 8 + 2 * tig], bias[head * 32 + 1 * 8 + 2 * tig],
                          bias[head * 32 + 2 * 8 + 2 * tig], bias[head * 32 + 3 * 8 + 2 * tig] };
    const float by[4] = { bias[head * 32 + 0 * 8 + 2 * tig + 1], bias[head * 32 + 1 * 8 + 2 * tig + 1],
                          bias[head * 32 + 2 * 8 + 2 * tig + 1], bias[head * 32 + 3 * 8 + 2 * tig + 1] };

#pragma unroll
    for (int mt = 0; mt < 4; mt++) {
        // store acc into staging
#pragma unroll
        for (int nt = 0; nt < 4; nt++) {
#pragma unroll
            for (int rr = 0; rr < 2; rr++) {
                int r = tg + rr * 8;                 // 0..15
                __half2 v = __floats2half2_rn(acc[mt][nt][rr * 2 + 0] + bx[nt],
                                              acc[mt][nt][rr * 2 + 1] + by[nt]);
                *reinterpret_cast<__half2*>(&stg[r * STG_ROW + nt * 8 + 2 * tig]) = v;
            }
        }
        __syncwarp();
        // write out: 16 rows x 64B, 4 lanes per row (STG.128), 2 passes
#pragma unroll
        for (int pass = 0; pass < 2; pass++) {
            int t    = pass * 32 + lane;             // 0..63
            int row  = t >> 2;                       // 0..15
            int c16  = (t & 3) * 8;                  // half offset within row
            int pixr = block_m + wm * 64 + mt * 16 + row;
            if (pixr < M) {
                int b = pixr / NV;
                int n = pixr - b * NV;
                uint4 v = *reinterpret_cast<const uint4*>(&stg[row * STG_ROW + c16]);
                *reinterpret_cast<uint4*>(
                    g_v_h + ((size_t)(b * HEADS + head) * NV + n) * DIM + c16) = v;
            }
        }
        __syncwarp();
    }
}

// ===========================================================================
// tf32 mma.sync GEMM for modes 1,2 (unchanged).
// ===========================================================================
__device__ __forceinline__ uint32_t f2tf32(float f) {
    uint32_t u;
    asm("cvt.rna.tf32.f32 %0, %1;" : "=r"(u) : "f"(f));
    return u;
}

__device__ __forceinline__ void mma_tf32(float& d0, float& d1, float& d2, float& d3,
                                         uint32_t a0, uint32_t a1, uint32_t a2, uint32_t a3,
                                         uint32_t b0, uint32_t b1) {
    asm volatile("mma.sync.aligned.m16n8k8.row.col.f32.tf32.tf32.f32 "
                 "{%0,%1,%2,%3},{%4,%5,%6,%7},{%8,%9},{%0,%1,%2,%3};"
                 : "+f"(d0), "+f"(d1), "+f"(d2), "+f"(d3)
                 : "r"(a0), "r"(a1), "r"(a2), "r"(a3), "r"(b0), "r"(b1));
}

#define AS_STRIDE 36
#define BS_STRIDE 136

template <int MODE>
__global__ __launch_bounds__(256)
void gemm_tc(const float* __restrict__ Aext, const float* __restrict__ A2,
             const float* __restrict__ B1,  const float* __restrict__ B2,
             const float* __restrict__ bias1, const float* __restrict__ bias2,
             const float* __restrict__ addsrc, float* __restrict__ Cext, int M)
{
    __shared__ uint32_t As[128][AS_STRIDE];
    __shared__ uint32_t Bsm[32][BS_STRIDE];

    const float* A = (MODE == 2) ? g_att : Aext;

    const int tid  = threadIdx.x;
    const int lane = tid & 31;
    const int warp = tid >> 5;
    const int wm   = warp >> 2;
    const int wn   = warp & 3;
    const int tg   = lane >> 2;
    const int tig  = lane & 3;

    const int block_m = blockIdx.y * 128;
    const int block_n = blockIdx.x * 128;

    float acc[4][4][4];
#pragma unroll
    for (int i = 0; i < 4; i++)
#pragma unroll
        for (int j = 0; j < 4; j++)
#pragma unroll
            for (int r = 0; r < 4; r++) acc[i][j][r] = 0.f;

    float4 aS[4], bS[4];
    const int a_row0 = tid >> 3;
    const int a_c4   = (tid & 7) * 4;
    const int b_k0   = tid >> 5;
    const int b_n4   = lane * 4;

    auto ldgA = [&](int k0) {
#pragma unroll
        for (int i = 0; i < 4; i++) {
            int gr = block_m + a_row0 + i * 32;
            float4 v = make_float4(0.f, 0.f, 0.f, 0.f);
            if (gr < M) {
                v = *reinterpret_cast<const float4*>(A + (size_t)gr * 256 + k0 + a_c4);
                if (MODE == 1) {
                    float4 v2 = *reinterpret_cast<const float4*>(A2 + (size_t)gr * 256 + k0 + a_c4);
                    v.x += v2.x; v.y += v2.y; v.z += v2.z; v.w += v2.w;
                }
            }
            aS[i] = v;
        }
    };
    auto ldgB = [&](int k0) {
#pragma unroll
        for (int i = 0; i < 4; i++) {
            int krow = b_k0 + i * 8;
            int gc   = block_n + b_n4;
            float4 v;
            if (MODE == 1) {
                if (gc < OFF_N) v = *reinterpret_cast<const float4*>(B1 + (size_t)(k0 + krow) * OFF_N + gc);
                else            v = *reinterpret_cast<const float4*>(B2 + (size_t)(k0 + krow) * 128 + (gc - OFF_N));
            } else {
                v = *reinterpret_cast<const float4*>(B1 + (size_t)(k0 + krow) * 256 + gc);
            }
            bS[i] = v;
        }
    };
    auto sts = [&]() {
#pragma unroll
        for (int i = 0; i < 4; i++) {
            uint4 u;
            u.x = f2tf32(aS[i].x); u.y = f2tf32(aS[i].y);
            u.z = f2tf32(aS[i].z); u.w = f2tf32(aS[i].w);
            *reinterpret_cast<uint4*>(&As[a_row0 + i * 32][a_c4]) = u;
        }
#pragma unroll
        for (int i = 0; i < 4; i++) {
            uint4 u;
            u.x = f2tf32(bS[i].x); u.y = f2tf32(bS[i].y);
            u.z = f2tf32(bS[i].z); u.w = f2tf32(bS[i].w);
            *reinterpret_cast<uint4*>(&Bsm[b_k0 + i * 8][b_n4]) = u;
        }
    };

    ldgA(0); ldgB(0);

    for (int k0 = 0; k0 < 256; k0 += 32) {
        sts();
        __syncthreads();
        if (k0 + 32 < 256) { ldgA(k0 + 32); ldgB(k0 + 32); }

#pragma unroll
        for (int ks = 0; ks < 4; ks++) {
            const int k = ks * 8;
            uint32_t a[4][4], b[4][2];
#pragma unroll
            for (int mt = 0; mt < 4; mt++) {
                int m = wm * 64 + mt * 16 + tg;
                a[mt][0] = As[m][k + tig];
                a[mt][1] = As[m + 8][k + tig];
                a[mt][2] = As[m][k + tig + 4];
                a[mt][3] = As[m + 8][k + tig + 4];
            }
#pragma unroll
            for (int nt = 0; nt < 4; nt++) {
                int n = wn * 32 + nt * 8 + tg;
                b[nt][0] = Bsm[k + tig][n];
                b[nt][1] = Bsm[k + tig + 4][n];
            }
#pragma unroll
            for (int mt = 0; mt < 4; mt++)
#pragma unroll
                for (int nt = 0; nt < 4; nt++)
                    mma_tf32(acc[mt][nt][0], acc[mt][nt][1], acc[mt][nt][2], acc[mt][nt][3],
                             a[mt][0], a[mt][1], a[mt][2], a[mt][3],
                             b[nt][0], b[nt][1]);
        }
        __syncthreads();
    }

#pragma unroll
    for (int mt = 0; mt < 4; mt++) {
#pragma unroll
        for (int nt = 0; nt < 4; nt++) {
            int gc = block_n + wn * 32 + nt * 8 + 2 * tig;
            float bx, by;
            if (MODE == 1) {
                bx = (gc < OFF_N) ? bias1[gc] : bias2[gc - OFF_N];
                by = (gc + 1 < OFF_N) ? bias1[gc + 1] : bias2[gc + 1 - OFF_N];
            } else {
                bx = bias1[gc]; by = bias1[gc + 1];
            }
#pragma unroll
            for (int rr = 0; rr < 2; rr++) {
                int gr = block_m + wm * 64 + mt * 16 + tg + rr * 8;
                if (gr >= M) continue;
                float ox = acc[mt][nt][rr * 2 + 0] + bx;
                float oy = acc[mt][nt][rr * 2 + 1] + by;
                if (MODE == 1) {
                    float2 o; o.x = ox; o.y = oy;
                    *reinterpret_cast<float2*>(g_qo + (size_t)gr * QO_N + gc) = o;
                } else {
                    const float2 idv = *reinterpret_cast<const float2*>(addsrc + (size_t)gr * 256 + gc);
                    float2 o; o.x = ox + idv.x; o.y = oy + idv.y;
                    *reinterpret_cast<float2*>(Cext + (size_t)gr * 256 + gc) = o;
                }
            }
        }
    }
}

// ===========================================================================
// Sampling v3 (R9 version — 40.2 µs measured).
// ===========================================================================
__global__ __launch_bounds__(256)
void sample_kernel3(const float* __restrict__ ref, const float* __restrict__ lro)
{
    int gwarp = (blockIdx.x * blockDim.x + threadIdx.x) >> 5;
    int lane  = threadIdx.x & 31;
    int hp    = gwarp & 3;
    int bq    = gwarp >> 2;
    if (bq >= BS * NQ) return;
    int b  = bq / NQ;
    int hi = lane >> 4;
    int li = lane & 15;
    int h  = hp * 2 + hi;

    const float* row = g_qo + (size_t)bq * QO_N;

    float logit = row[OFF_N + h * 16 + li];
    float m = logit;
#pragma unroll
    for (int s = 8; s; s >>= 1) m = fmaxf(m, __shfl_xor_sync(0xffffffffu, m, s));
    float e = expf(logit - m);
    float ss = e;
#pragma unroll
    for (int s = 8; s; s >>= 1) ss += __shfl_xor_sync(0xffffffffu, ss, s);
    float a = e / ss;

    int l = li >> 2;
    int p = li & 3;
    int W = c_W[l], H = c_H[l], st = c_start[l];

    float rx = ref[(size_t)(bq * 4 + l) * 2 + 0];
    float ry = ref[(size_t)(bq * 4 + l) * 2 + 1];
    float lx = lro[(size_t)(bq * 8 + h) * 2 + 0];
    float ly = lro[(size_t)(bq * 8 + h) * 2 + 1];
    float ox = row[((h * 4 + l) * 4 + p) * 2 + 0];
    float oy = row[((h * 4 + l) * 4 + p) * 2 + 1];

    float px = (rx + ox * c_invW[l] + lx) * c_Wf[l] - 0.5f;
    float py = (ry + oy * c_invH[l] + ly) * c_Hf[l] - 0.5f;

    float x0f = floorf(px), y0f = floorf(py);
    int   x0  = (int)x0f,   y0  = (int)y0f;
    float wx1 = px - x0f, wx0 = 1.f - wx1;
    float wy1 = py - y0f, wy0 = 1.f - wy1;

    float vx0 = (x0 >= 0 && x0 < W)         ? wx0 : 0.f;
    float vx1 = (x0 + 1 >= 0 && x0 + 1 < W) ? wx1 : 0.f;
    float vy0 = (y0 >= 0 && y0 < H)         ? wy0 : 0.f;
    float vy1 = (y0 + 1 >= 0 && y0 + 1 < H) ? wy1 : 0.f;

    __half2 hAB = __floats2half2_rn(a * vy0 * vx0, a * vy0 * vx1);
    __half2 hCD = __floats2half2_rn(a * vy1 * vx0, a * vy1 * vx1);
    uint32_t uAB = *reinterpret_cast<uint32_t*>(&hAB);
    uint32_t uCD = *reinterpret_cast<uint32_t*>(&hCD);

    int cx0 = min(max(x0, 0), W - 1);
    int cx1 = min(max(x0 + 1, 0), W - 1);
    int cy0 = min(max(y0, 0), H - 1);
    int cy1 = min(max(y0 + 1, 0), H - 1);

    int idxPack = (st + cy0 * W + cx0) * 16
                | ((cx1 - cx0) << 20)
                | ((cy1 - cy0) << 21);

    const __half2* vb2 = reinterpret_cast<const __half2*>(g_v_h)
                       + (size_t)(b * HEADS + h) * (NV * 16) + li;
    float accx = 0.f, accy = 0.f;
    const int srcbase = lane & 16;
    const int Wtab16[4] = {160 * 16, 80 * 16, 40 * 16, 20 * 16};

#pragma unroll
    for (int j = 0; j < 16; j++) {
        int src = srcbase + j;
        uint32_t pAB = __shfl_sync(0xffffffffu, uAB, src);
        uint32_t pCD = __shfl_sync(0xffffffffu, uCD, src);
        int      pk  = __shfl_sync(0xffffffffu, idxPack, src);

        int i00 = pk & 0xFFFFF;
        int dx  = ((pk >> 20) & 1) * 16;
        int dy  = ((pk >> 21) & 1) * Wtab16[j >> 2];

        float2 wab = __half22float2(*reinterpret_cast<const __half2*>(&pAB));
        float2 wcd = __half22float2(*reinterpret_cast<const __half2*>(&pCD));

        float2 f00 = __half22float2(vb2[i00]);
        float2 f10 = __half22float2(vb2[i00 + dx]);
        float2 f01 = __half22float2(vb2[i00 + dy]);
        float2 f11 = __half22float2(vb2[i00 + dx + dy]);

        accx += wab.x * f00.x + wab.y * f10.x + wcd.x * f01.x + wcd.y * f11.x;
        accy += wab.x * f00.y + wab.y * f10.y + wcd.x * f01.y + wcd.y * f11.y;
    }

    float2* outp = reinterpret_cast<float2*>(g_att + (size_t)bq * EMBED + h * DIM) + li;
    *outp = make_float2(accx, accy);
}

// ---------------------------------------------------------------------------
extern "C" void kernel_launch(void* const* d_in, const int* in_sizes, int n_in,
                              void* d_out, int out_size)
{
    (void)in_sizes; (void)n_in; (void)out_size;
    const float* query = (const float*)d_in[0];
    const float* value = (const float*)d_in[1];
    const float* qpos  = (const float*)d_in[2];
    const float* ref   = (const float*)d_in[3];
    const float* lro   = (const float*)d_in[4];
    const float* Wv    = (const float*)d_in[6];
    const float* bv    = (const float*)d_in[7];
    const float* Wo    = (const float*)d_in[8];
    const float* bo    = (const float*)d_in[9];
    const float* Wa    = (const float*)d_in[10];
    const float* ba    = (const float*)d_in[11];
    const float* Wout  = (const float*)d_in[12];
    const float* bout  = (const float*)d_in[13];
    float* out = (float*)d_out;

    conv_wv<<<128, 256>>>(Wv);
    {
        dim3 g(2, (BS * NV + 127) / 128);
        gemm_v_bf16<<<g, 256>>>(value, bv, BS * NV);
    }
    {
        dim3 g(3, (BS * NQ + 127) / 128);
        gemm_tc<1><<<g, 256>>>(query, qpos, Wo, Wa, bo, ba, nullptr, nullptr, BS * NQ);
    }
    {
        int total_warps = BS * NQ * 4;
        sample_kernel3<<<(total_warps * 32 + 255) / 256, 256>>>(ref, lro);
    }
    {
        dim3 g(2, (BS * NQ + 127) / 128);
        gemm_tc<2><<<g, 256>>>(nullptr, nullptr, Wout, nullptr, bout, nullptr, query, out, BS * NQ);
    }
}